// round 2
// baseline (speedup 1.0000x reference)
#include <cuda_runtime.h>

#define FULLMASK 0xffffffffu
#define DIN   128
#define HC    256
#define NHEAD 4
#define CH    64
#define NMAX  50016
#define EMAX  900000

typedef unsigned long long u64;

// ---------------- scratch (device globals; no allocation allowed) -----------
__device__ float g_h[(size_t)NMAX * HC];    // GEMM output / layer-2 features
__device__ float g_act[(size_t)NMAX * HC];  // layer-1 activations
__device__ float g_asrc[NMAX * NHEAD];
__device__ float g_adst[NMAX * NHEAD];
__device__ int   g_rowptr[NMAX + 1];
__device__ int   g_deg[NMAX];
__device__ int   g_cursor[NMAX];
__device__ int   g_csrc[EMAX];

// ---------------- f32x2 packed-FMA helpers ----------------------------------
static __device__ __forceinline__ u64 pack_dup(float v) {
    u64 r; asm("mov.b64 %0,{%1,%1};" : "=l"(r) : "f"(v)); return r;
}
static __device__ __forceinline__ void ffma2(u64& c, u64 a, u64 b) {
    asm("fma.rn.f32x2 %0,%1,%2,%0;" : "+l"(c) : "l"(a), "l"(b));
}
static __device__ __forceinline__ float2 unpack2(u64 v) {
    float2 f; asm("mov.b64 {%0,%1},%2;" : "=f"(f.x), "=f"(f.y) : "l"(v)); return f;
}

// ---------------- helpers ---------------------------------------------------
static __device__ __forceinline__ float leaky(float x) { return fmaxf(x, 0.2f * x); }
static __device__ __forceinline__ float sel4(float4 v, int h) {
    return h == 0 ? v.x : (h == 1 ? v.y : (h == 2 ? v.z : v.w));
}

// ---------------- CSR build --------------------------------------------------
__global__ void zero2_kernel(int* a, int* b, int n) {
    int i = blockIdx.x * blockDim.x + threadIdx.x;
    if (i < n) { a[i] = 0; b[i] = 0; }
}

__global__ void hist_kernel(const int* __restrict__ ei, int E, int* __restrict__ deg) {
    int i = blockIdx.x * blockDim.x + threadIdx.x;
    if (i < E) atomicAdd(&deg[ei[E + i]], 1);
}

__global__ void scan_kernel(const int* __restrict__ deg, int* __restrict__ rowptr, int n) {
    __shared__ int partials[1024];
    int tid = threadIdx.x;
    int per = (n + 1023) >> 10;
    int start = tid * per;
    int end = min(start + per, n);
    int s = 0;
    for (int i = start; i < end; i++) s += deg[i];
    partials[tid] = s;
    __syncthreads();
    for (int d = 1; d < 1024; d <<= 1) {
        int v = (tid >= d) ? partials[tid - d] : 0;
        __syncthreads();
        partials[tid] += v;
        __syncthreads();
    }
    int run = partials[tid] - s;  // exclusive prefix
    for (int i = start; i < end; i++) { rowptr[i] = run; run += deg[i]; }
    if (end == n) rowptr[n] = run;
}

__global__ void scatter_kernel(const int* __restrict__ ei, int E,
                               const int* __restrict__ rowptr,
                               int* __restrict__ cursor, int* __restrict__ csrc) {
    int i = blockIdx.x * blockDim.x + threadIdx.x;
    if (i < E) {
        int d = ei[E + i];
        int pos = atomicAdd(&cursor[d], 1);
        csrc[rowptr[d] + pos] = ei[i];
    }
}

// ---------------- FFMA2 GEMM + fused attention coefficients ------------------
// C[M,Nn] = A[M,K] @ B[K,Nn]; also asrc[m,h]/adst[m,h] = dot(C[m, h*64:(h+1)*64], att)
#define BM 128
#define BN 128
#define BK 16
#define APAD 132

__global__ __launch_bounds__(256, 2) void gemm_att_kernel(
    const float* __restrict__ A, const float* __restrict__ B, float* __restrict__ C,
    const float* __restrict__ attS, const float* __restrict__ attD,
    float* __restrict__ asrc, float* __restrict__ adst,
    int M, int K, int Nn) {
    __shared__ float As[BK * APAD];
    __shared__ float Bs[BK * BN];
    const int t = threadIdx.x;
    const int tx = t & 15, ty = t >> 4;
    const int m0 = blockIdx.x * BM, n0 = blockIdx.y * BN;

    u64 acc[8][4];
#pragma unroll
    for (int i = 0; i < 8; i++)
#pragma unroll
        for (int j = 0; j < 4; j++) acc[i][j] = 0ull;

    for (int kt = 0; kt < K; kt += BK) {
        // load A tile (transposed to [k][m], padded)
#pragma unroll
        for (int L = 0; L < 2; L++) {
            int f = t + L * 256;
            int row = f >> 2;
            int kg = (f & 3) << 2;
            float4 av = make_float4(0.f, 0.f, 0.f, 0.f);
            int m = m0 + row;
            if (m < M) av = *(const float4*)(A + (size_t)m * K + kt + kg);
            As[(kg + 0) * APAD + row] = av.x;
            As[(kg + 1) * APAD + row] = av.y;
            As[(kg + 2) * APAD + row] = av.z;
            As[(kg + 3) * APAD + row] = av.w;
        }
        // load B tile [k][n]
        {
            int row = t >> 4;
            int cg = (t & 15) << 3;
            float4 b0 = *(const float4*)(B + (size_t)(kt + row) * Nn + n0 + cg);
            float4 b1 = *(const float4*)(B + (size_t)(kt + row) * Nn + n0 + cg + 4);
            *(float4*)(Bs + row * BN + cg) = b0;
            *(float4*)(Bs + row * BN + cg + 4) = b1;
        }
        __syncthreads();
#pragma unroll
        for (int kk = 0; kk < BK; kk++) {
            float4 a0 = *(const float4*)(As + kk * APAD + ty * 8);
            float4 a1 = *(const float4*)(As + kk * APAD + ty * 8 + 4);
            ulonglong2 q0 = *(const ulonglong2*)(Bs + kk * BN + tx * 8);
            ulonglong2 q1 = *(const ulonglong2*)(Bs + kk * BN + tx * 8 + 4);
            u64 bp[4] = {q0.x, q0.y, q1.x, q1.y};
            float av[8] = {a0.x, a0.y, a0.z, a0.w, a1.x, a1.y, a1.z, a1.w};
#pragma unroll
            for (int i = 0; i < 8; i++) {
                u64 ad = pack_dup(av[i]);
#pragma unroll
                for (int j = 0; j < 4; j++) ffma2(acc[i][j], ad, bp[j]);
            }
        }
        __syncthreads();
    }

    // epilogue: store C + fused per-head attention dot products
    const int lane = t & 31;
    float4 s0 = *(const float4*)(attS + n0 + tx * 8);
    float4 s1 = *(const float4*)(attS + n0 + tx * 8 + 4);
    float4 d0 = *(const float4*)(attD + n0 + tx * 8);
    float4 d1 = *(const float4*)(attD + n0 + tx * 8 + 4);
    const int head = 2 * blockIdx.y + ((lane >> 3) & 1);

#pragma unroll
    for (int i = 0; i < 8; i++) {
        int m = m0 + ty * 8 + i;
        float c[8];
#pragma unroll
        for (int j = 0; j < 4; j++) {
            float2 f = unpack2(acc[i][j]);
            c[2 * j] = f.x;
            c[2 * j + 1] = f.y;
        }
        if (m < M) {
            *(float4*)(C + (size_t)m * Nn + n0 + tx * 8) = make_float4(c[0], c[1], c[2], c[3]);
            *(float4*)(C + (size_t)m * Nn + n0 + tx * 8 + 4) = make_float4(c[4], c[5], c[6], c[7]);
        }
        float ps = c[0] * s0.x + c[1] * s0.y + c[2] * s0.z + c[3] * s0.w +
                   c[4] * s1.x + c[5] * s1.y + c[6] * s1.z + c[7] * s1.w;
        float pd = c[0] * d0.x + c[1] * d0.y + c[2] * d0.z + c[3] * d0.w +
                   c[4] * d1.x + c[5] * d1.y + c[6] * d1.z + c[7] * d1.w;
#pragma unroll
        for (int o = 1; o < 8; o <<= 1) {
            ps += __shfl_xor_sync(FULLMASK, ps, o);
            pd += __shfl_xor_sync(FULLMASK, pd, o);
        }
        if ((lane & 7) == 0 && m < M) {
            asrc[m * 4 + head] = ps;
            adst[m * 4 + head] = pd;
        }
    }
}

// ---------------- per-node aggregation core (phases 1-3) ---------------------
static __device__ __forceinline__ void agg_core(const float* __restrict__ hbuf,
                                                const float* __restrict__ asrc,
                                                const float* __restrict__ adst,
                                                const int* __restrict__ rowptr,
                                                const int* __restrict__ csrc,
                                                int gw, int lane,
                                                float4& acc0, float4& acc1) {
    int hsel = lane >> 3;
    int beg = rowptr[gw], end = rowptr[gw + 1];
    float4 ad = *(const float4*)(adst + gw * 4);

    // phase 1: segment max (per head)
    float4 mx = make_float4(-1e30f, -1e30f, -1e30f, -1e30f);
    for (int j = beg + lane; j < end; j += 32) {
        int s = csrc[j];
        float4 as = *(const float4*)(asrc + s * 4);
        mx.x = fmaxf(mx.x, leaky(as.x + ad.x));
        mx.y = fmaxf(mx.y, leaky(as.y + ad.y));
        mx.z = fmaxf(mx.z, leaky(as.z + ad.z));
        mx.w = fmaxf(mx.w, leaky(as.w + ad.w));
    }
#pragma unroll
    for (int o = 16; o; o >>= 1) {
        mx.x = fmaxf(mx.x, __shfl_xor_sync(FULLMASK, mx.x, o));
        mx.y = fmaxf(mx.y, __shfl_xor_sync(FULLMASK, mx.y, o));
        mx.z = fmaxf(mx.z, __shfl_xor_sync(FULLMASK, mx.z, o));
        mx.w = fmaxf(mx.w, __shfl_xor_sync(FULLMASK, mx.w, o));
    }

    // phase 2: exp-sum
    float4 sm = make_float4(0.f, 0.f, 0.f, 0.f);
    for (int j = beg + lane; j < end; j += 32) {
        int s = csrc[j];
        float4 as = *(const float4*)(asrc + s * 4);
        sm.x += __expf(leaky(as.x + ad.x) - mx.x);
        sm.y += __expf(leaky(as.y + ad.y) - mx.y);
        sm.z += __expf(leaky(as.z + ad.z) - mx.z);
        sm.w += __expf(leaky(as.w + ad.w) - mx.w);
    }
#pragma unroll
    for (int o = 16; o; o >>= 1) {
        sm.x += __shfl_xor_sync(FULLMASK, sm.x, o);
        sm.y += __shfl_xor_sync(FULLMASK, sm.y, o);
        sm.z += __shfl_xor_sync(FULLMASK, sm.z, o);
        sm.w += __shfl_xor_sync(FULLMASK, sm.w, o);
    }
    float4 inv = make_float4(1.f / (sm.x + 1e-16f), 1.f / (sm.y + 1e-16f),
                             1.f / (sm.z + 1e-16f), 1.f / (sm.w + 1e-16f));
    float mh = sel4(mx, hsel), ih = sel4(inv, hsel), adh = sel4(ad, hsel);

    // phase 3: weighted gather-accumulate (whole warp walks each edge)
    acc0 = make_float4(0.f, 0.f, 0.f, 0.f);
    acc1 = make_float4(0.f, 0.f, 0.f, 0.f);
    const int cbase = lane * 8;
    for (int j = beg; j < end; j++) {
        int s = csrc[j];
        float as = asrc[s * 4 + hsel];
        float alpha = __expf(leaky(as + adh) - mh) * ih;
        const float4* hp = (const float4*)(hbuf + (size_t)s * HC + cbase);
        float4 v0 = hp[0], v1 = hp[1];
        acc0.x = fmaf(v0.x, alpha, acc0.x);
        acc0.y = fmaf(v0.y, alpha, acc0.y);
        acc0.z = fmaf(v0.z, alpha, acc0.z);
        acc0.w = fmaf(v0.w, alpha, acc0.w);
        acc1.x = fmaf(v1.x, alpha, acc1.x);
        acc1.y = fmaf(v1.y, alpha, acc1.y);
        acc1.z = fmaf(v1.z, alpha, acc1.z);
        acc1.w = fmaf(v1.w, alpha, acc1.w);
    }
}

// layer 1: concat=True epilogue (bias + relu -> [N,256])
__global__ __launch_bounds__(256) void agg1_kernel(const float* __restrict__ hbuf,
                                                   const float* __restrict__ asrc,
                                                   const float* __restrict__ adst,
                                                   const int* __restrict__ rowptr,
                                                   const int* __restrict__ csrc,
                                                   const float* __restrict__ bias,
                                                   float* __restrict__ outbuf, int N) {
    int gw = (blockIdx.x * blockDim.x + threadIdx.x) >> 5;
    int lane = threadIdx.x & 31;
    if (gw >= N) return;
    float4 acc0, acc1;
    agg_core(hbuf, asrc, adst, rowptr, csrc, gw, lane, acc0, acc1);
    int cbase = lane * 8;
    float4 b0 = *(const float4*)(bias + cbase);
    float4 b1 = *(const float4*)(bias + cbase + 4);
    float* op = outbuf + (size_t)gw * HC + cbase;
    ((float4*)op)[0] = make_float4(fmaxf(acc0.x + b0.x, 0.f), fmaxf(acc0.y + b0.y, 0.f),
                                   fmaxf(acc0.z + b0.z, 0.f), fmaxf(acc0.w + b0.w, 0.f));
    ((float4*)op)[1] = make_float4(fmaxf(acc1.x + b1.x, 0.f), fmaxf(acc1.y + b1.y, 0.f),
                                   fmaxf(acc1.z + b1.z, 0.f), fmaxf(acc1.w + b1.w, 0.f));
}

// layer 2: head-mean + bias + relu + softmax(64) -> [N,64]
__global__ __launch_bounds__(256) void agg2_kernel(const float* __restrict__ hbuf,
                                                   const float* __restrict__ asrc,
                                                   const float* __restrict__ adst,
                                                   const int* __restrict__ rowptr,
                                                   const int* __restrict__ csrc,
                                                   const float* __restrict__ bias,
                                                   float* __restrict__ outp, int N) {
    int gw = (blockIdx.x * blockDim.x + threadIdx.x) >> 5;
    int lane = threadIdx.x & 31;
    if (gw >= N) return;
    float4 acc0, acc1;
    agg_core(hbuf, asrc, adst, rowptr, csrc, gw, lane, acc0, acc1);

    float r[8] = {acc0.x, acc0.y, acc0.z, acc0.w, acc1.x, acc1.y, acc1.z, acc1.w};
#pragma unroll
    for (int k = 0; k < 8; k++) {
        r[k] += __shfl_xor_sync(FULLMASK, r[k], 8);
        r[k] += __shfl_xor_sync(FULLMASK, r[k], 16);
    }
    int cp = (lane & 7) * 8;
    float4 b0 = *(const float4*)(bias + cp);
    float4 b1 = *(const float4*)(bias + cp + 4);
    float bb[8] = {b0.x, b0.y, b0.z, b0.w, b1.x, b1.y, b1.z, b1.w};
    float lm = -1e30f;
#pragma unroll
    for (int k = 0; k < 8; k++) {
        r[k] = fmaxf(0.25f * r[k] + bb[k], 0.f);
        lm = fmaxf(lm, r[k]);
    }
#pragma unroll
    for (int o = 4; o; o >>= 1) lm = fmaxf(lm, __shfl_xor_sync(FULLMASK, lm, o));
    float ls = 0.f;
#pragma unroll
    for (int k = 0; k < 8; k++) { r[k] = __expf(r[k] - lm); ls += r[k]; }
#pragma unroll
    for (int o = 4; o; o >>= 1) ls += __shfl_xor_sync(FULLMASK, ls, o);
    float invs = 1.f / ls;
    if (lane < 8) {
        float* op = outp + (size_t)gw * CH + lane * 8;
        ((float4*)op)[0] = make_float4(r[0] * invs, r[1] * invs, r[2] * invs, r[3] * invs);
        ((float4*)op)[1] = make_float4(r[4] * invs, r[5] * invs, r[6] * invs, r[7] * invs);
    }
}

// ---------------- launch -----------------------------------------------------
extern "C" void kernel_launch(void* const* d_in, const int* in_sizes, int n_in,
                              void* d_out, int out_size) {
    const float* x   = (const float*)d_in[0];
    const int*   ei  = (const int*)d_in[1];
    const float* W1  = (const float*)d_in[2];
    const float* as1 = (const float*)d_in[3];
    const float* ad1 = (const float*)d_in[4];
    const float* b1  = (const float*)d_in[5];
    const float* W2  = (const float*)d_in[6];
    const float* as2 = (const float*)d_in[7];
    const float* ad2 = (const float*)d_in[8];
    const float* b2  = (const float*)d_in[9];
    float* out = (float*)d_out;

    const int N = in_sizes[0] / DIN;
    const int E = in_sizes[1] / 2;

    float *dH, *dAct, *dAs, *dAd;
    int *dRow, *dDeg, *dCur, *dCsr;
    cudaGetSymbolAddress((void**)&dH, g_h);
    cudaGetSymbolAddress((void**)&dAct, g_act);
    cudaGetSymbolAddress((void**)&dAs, g_asrc);
    cudaGetSymbolAddress((void**)&dAd, g_adst);
    cudaGetSymbolAddress((void**)&dRow, g_rowptr);
    cudaGetSymbolAddress((void**)&dDeg, g_deg);
    cudaGetSymbolAddress((void**)&dCur, g_cursor);
    cudaGetSymbolAddress((void**)&dCsr, g_csrc);

    // CSR build (by destination node)
    zero2_kernel<<<(N + 255) / 256, 256>>>(dDeg, dCur, N);
    hist_kernel<<<(E + 255) / 256, 256>>>(ei, E, dDeg);
    scan_kernel<<<1, 1024>>>(dDeg, dRow, N);
    scatter_kernel<<<(E + 255) / 256, 256>>>(ei, E, dRow, dCur, dCsr);

    const int warpBlocks = (N * 32 + 255) / 256;
    dim3 gg((N + BM - 1) / BM, HC / BN);

    // layer 1 (GEMM + fused attention coefficients)
    gemm_att_kernel<<<gg, 256>>>(x, W1, dH, as1, ad1, dAs, dAd, N, DIN, HC);
    agg1_kernel<<<warpBlocks, 256>>>(dH, dAs, dAd, dRow, dCsr, b1, dAct, N);

    // layer 2
    gemm_att_kernel<<<gg, 256>>>(dAct, W2, dH, as2, ad2, dAs, dAd, N, HC, HC);
    agg2_kernel<<<warpBlocks, 256>>>(dH, dAs, dAd, dRow, dCsr, b2, out, N);
}

// round 3
// speedup vs baseline: 1.7541x; 1.7541x over previous
#include <cuda_runtime.h>

#define FULLMASK 0xffffffffu
#define DIN   128
#define HC    256
#define NHEAD 4
#define CH    64
#define NMAX  50016
#define EMAX  900000

// ---------------- scratch (device globals; no allocation allowed) -----------
__device__ float g_h[(size_t)NMAX * HC];    // GEMM output / layer-2 features
__device__ float g_act[(size_t)NMAX * HC];  // layer-1 activations
__device__ float g_asrc[NMAX * NHEAD];
__device__ float g_adst[NMAX * NHEAD];
__device__ int   g_rowptr[NMAX + 1];
__device__ int   g_deg[NMAX];
__device__ int   g_cursor[NMAX];
__device__ int   g_csrc[EMAX];

// ---------------- helpers ---------------------------------------------------
static __device__ __forceinline__ float leaky(float x) { return fmaxf(x, 0.2f * x); }
static __device__ __forceinline__ float sel4(float4 v, int h) {
    return h == 0 ? v.x : (h == 1 ? v.y : (h == 2 ? v.z : v.w));
}

// tf32 split: v = hi + lo, hi = round-to-tf32(v), lo exact fp32 residual
static __device__ __forceinline__ void tfsplit(float v, unsigned& hi, unsigned& lo) {
    unsigned h;
    asm("cvt.rna.tf32.f32 %0, %1;" : "=r"(h) : "f"(v));
    hi = h;
    lo = __float_as_uint(v - __uint_as_float(h));
}

static __device__ __forceinline__ void mma8(float* d, const unsigned* a,
                                            unsigned b0, unsigned b1) {
    asm volatile(
        "mma.sync.aligned.m16n8k8.row.col.f32.tf32.tf32.f32 "
        "{%0,%1,%2,%3},{%4,%5,%6,%7},{%8,%9},{%0,%1,%2,%3};"
        : "+f"(d[0]), "+f"(d[1]), "+f"(d[2]), "+f"(d[3])
        : "r"(a[0]), "r"(a[1]), "r"(a[2]), "r"(a[3]), "r"(b0), "r"(b1));
}

// ---------------- CSR build --------------------------------------------------
__global__ void zero2_kernel(int* a, int* b, int n) {
    int i = blockIdx.x * blockDim.x + threadIdx.x;
    if (i < n) { a[i] = 0; b[i] = 0; }
}

__global__ void hist_kernel(const int* __restrict__ ei, int E, int* __restrict__ deg) {
    int i = blockIdx.x * blockDim.x + threadIdx.x;
    if (i < E) atomicAdd(&deg[ei[E + i]], 1);
}

__global__ void scan_kernel(const int* __restrict__ deg, int* __restrict__ rowptr, int n) {
    __shared__ int partials[1024];
    int tid = threadIdx.x;
    int per = (n + 1023) >> 10;
    int start = tid * per;
    int end = min(start + per, n);
    int s = 0;
    for (int i = start; i < end; i++) s += deg[i];
    partials[tid] = s;
    __syncthreads();
    for (int d = 1; d < 1024; d <<= 1) {
        int v = (tid >= d) ? partials[tid - d] : 0;
        __syncthreads();
        partials[tid] += v;
        __syncthreads();
    }
    int run = partials[tid] - s;  // exclusive prefix
    for (int i = start; i < end; i++) { rowptr[i] = run; run += deg[i]; }
    if (end == n) rowptr[n] = run;
}

__global__ void scatter_kernel(const int* __restrict__ ei, int E,
                               const int* __restrict__ rowptr,
                               int* __restrict__ cursor, int* __restrict__ csrc) {
    int i = blockIdx.x * blockDim.x + threadIdx.x;
    if (i < E) {
        int d = ei[E + i];
        int pos = atomicAdd(&cursor[d], 1);
        csrc[rowptr[d] + pos] = ei[i];
    }
}

// ---------------- tf32 split GEMM: C[M,Nn] = A[M,K] @ B[K,Nn] ---------------
// BM=128, BN=128, BK=32; 8 warps (4m x 2n), warp tile 32x64.
// A raw tile in smem padded to row stride 36 (bank-free frag loads),
// B raw tile stride 136. cp.async double buffered. hi/lo split at consume.
#define A_STRIDE 36
#define B_STRIDE 136
#define A_TILE   (128 * A_STRIDE)   // 4608 floats
#define B_TILE   (32 * B_STRIDE)    // 4352 floats
#define GEMM_SMEM ((2 * (A_TILE + B_TILE)) * 4)  // 71680 bytes

__global__ __launch_bounds__(256) void gemm_tf32_kernel(
    const float* __restrict__ A, const float* __restrict__ B,
    float* __restrict__ C, int M, int K, int Nn) {
    extern __shared__ float sm[];
    float* Abuf = sm;                 // 2 stages * A_TILE
    float* Bbuf = sm + 2 * A_TILE;    // 2 stages * B_TILE

    const int t = threadIdx.x;
    const int lane = t & 31;
    const int warpid = t >> 5;
    const int wm = warpid & 3;   // 0..3  (rows wm*32)
    const int wn = warpid >> 2;  // 0..1  (cols wn*64)
    const int m0 = blockIdx.x * 128;
    const int n0 = blockIdx.y * 128;
    const int g = lane >> 2, q = lane & 3;

    float acc[2][8][4];
#pragma unroll
    for (int mi = 0; mi < 2; mi++)
#pragma unroll
        for (int ni = 0; ni < 8; ni++)
#pragma unroll
            for (int w = 0; w < 4; w++) acc[mi][ni][w] = 0.f;

    const int ntiles = K >> 5;

    auto issue = [&](int tile, int stage) {
        const int kt = tile << 5;
        float* Ad = Abuf + stage * A_TILE;
        float* Bd = Bbuf + stage * B_TILE;
#pragma unroll
        for (int i = 0; i < 4; i++) {
            int idx = i * 256 + t;
            int m = idx >> 3, kq = idx & 7;
            bool valid = (m0 + m) < M;
            const float* src = A + (size_t)(valid ? (m0 + m) : 0) * K + kt + kq * 4;
            unsigned dst = (unsigned)__cvta_generic_to_shared(Ad + m * A_STRIDE + kq * 4);
            int sz = valid ? 16 : 0;
            asm volatile("cp.async.ca.shared.global [%0], [%1], 16, %2;"
                         :: "r"(dst), "l"(src), "r"(sz));
        }
#pragma unroll
        for (int i = 0; i < 4; i++) {
            int idx = i * 256 + t;
            int r = idx >> 5, cq = idx & 31;
            const float* src = B + (size_t)(kt + r) * Nn + n0 + cq * 4;
            unsigned dst = (unsigned)__cvta_generic_to_shared(Bd + r * B_STRIDE + cq * 4);
            asm volatile("cp.async.ca.shared.global [%0], [%1], 16;"
                         :: "r"(dst), "l"(src));
        }
        asm volatile("cp.async.commit_group;");
    };

    issue(0, 0);

    for (int tile = 0; tile < ntiles; tile++) {
        const int cur = tile & 1;
        if (tile + 1 < ntiles) {
            issue(tile + 1, cur ^ 1);
            asm volatile("cp.async.wait_group 1;");
        } else {
            asm volatile("cp.async.wait_group 0;");
        }
        __syncthreads();
        const float* As = Abuf + cur * A_TILE;
        const float* Bs = Bbuf + cur * B_TILE;

#pragma unroll
        for (int k8 = 0; k8 < 4; k8++) {
            const int kk = k8 * 8;
            unsigned ah[2][4], al[2][4];
#pragma unroll
            for (int mi = 0; mi < 2; mi++) {
                int rb = (wm * 32 + mi * 16 + g) * A_STRIDE + kk + q;
                float x0 = As[rb];
                float x1 = As[rb + 8 * A_STRIDE];
                float x2 = As[rb + 4];
                float x3 = As[rb + 8 * A_STRIDE + 4];
                tfsplit(x0, ah[mi][0], al[mi][0]);
                tfsplit(x1, ah[mi][1], al[mi][1]);
                tfsplit(x2, ah[mi][2], al[mi][2]);
                tfsplit(x3, ah[mi][3], al[mi][3]);
            }
#pragma unroll
            for (int ni = 0; ni < 8; ni++) {
                int cb = (kk + q) * B_STRIDE + wn * 64 + ni * 8 + g;
                float y0 = Bs[cb];
                float y1 = Bs[cb + 4 * B_STRIDE];
                unsigned bh0, bl0, bh1, bl1;
                tfsplit(y0, bh0, bl0);
                tfsplit(y1, bh1, bl1);
#pragma unroll
                for (int mi = 0; mi < 2; mi++) {
                    mma8(acc[mi][ni], ah[mi], bh0, bh1);
                    mma8(acc[mi][ni], ah[mi], bl0, bl1);
                    mma8(acc[mi][ni], al[mi], bh0, bh1);
                }
            }
        }
        __syncthreads();
    }

    // epilogue: store C
#pragma unroll
    for (int mi = 0; mi < 2; mi++) {
#pragma unroll
        for (int ni = 0; ni < 8; ni++) {
            int r0 = m0 + wm * 32 + mi * 16 + g;
            int cc = n0 + wn * 64 + ni * 8 + q * 2;
            if (r0 < M)
                *(float2*)(C + (size_t)r0 * Nn + cc) =
                    make_float2(acc[mi][ni][0], acc[mi][ni][1]);
            if (r0 + 8 < M)
                *(float2*)(C + (size_t)(r0 + 8) * Nn + cc) =
                    make_float2(acc[mi][ni][2], acc[mi][ni][3]);
        }
    }
}

// ---------------- attention coefficients: a_src/a_dst [N,4] ------------------
__global__ __launch_bounds__(256) void att_kernel(const float* __restrict__ hbuf,
                                                  const float* __restrict__ att_s,
                                                  const float* __restrict__ att_d,
                                                  float* __restrict__ asrc,
                                                  float* __restrict__ adst, int N) {
    int gw = (blockIdx.x * blockDim.x + threadIdx.x) >> 5;
    int lane = threadIdx.x & 31;
    if (gw >= N) return;
    int c = lane * 8;
    float4 h0 = *(const float4*)(hbuf + (size_t)gw * HC + c);
    float4 h1 = *(const float4*)(hbuf + (size_t)gw * HC + c + 4);
    float4 s0 = *(const float4*)(att_s + c);
    float4 s1 = *(const float4*)(att_s + c + 4);
    float4 d0 = *(const float4*)(att_d + c);
    float4 d1 = *(const float4*)(att_d + c + 4);
    float ps = h0.x * s0.x + h0.y * s0.y + h0.z * s0.z + h0.w * s0.w +
               h1.x * s1.x + h1.y * s1.y + h1.z * s1.z + h1.w * s1.w;
    float pd = h0.x * d0.x + h0.y * d0.y + h0.z * d0.z + h0.w * d0.w +
               h1.x * d1.x + h1.y * d1.y + h1.z * d1.z + h1.w * d1.w;
#pragma unroll
    for (int o = 1; o < 8; o <<= 1) {
        ps += __shfl_xor_sync(FULLMASK, ps, o);
        pd += __shfl_xor_sync(FULLMASK, pd, o);
    }
    if ((lane & 7) == 0) {
        int head = lane >> 3;
        asrc[gw * 4 + head] = ps;
        adst[gw * 4 + head] = pd;
    }
}

// ---------------- per-node aggregation core (phases 1-3) ---------------------
static __device__ __forceinline__ void agg_core(const float* __restrict__ hbuf,
                                                const float* __restrict__ asrc,
                                                const float* __restrict__ adst,
                                                const int* __restrict__ rowptr,
                                                const int* __restrict__ csrc,
                                                int gw, int lane,
                                                float4& acc0, float4& acc1) {
    int hsel = lane >> 3;
    int beg = rowptr[gw], end = rowptr[gw + 1];
    float4 ad = *(const float4*)(adst + gw * 4);

    // phase 1: segment max (per head)
    float4 mx = make_float4(-1e30f, -1e30f, -1e30f, -1e30f);
    for (int j = beg + lane; j < end; j += 32) {
        int s = csrc[j];
        float4 as = *(const float4*)(asrc + s * 4);
        mx.x = fmaxf(mx.x, leaky(as.x + ad.x));
        mx.y = fmaxf(mx.y, leaky(as.y + ad.y));
        mx.z = fmaxf(mx.z, leaky(as.z + ad.z));
        mx.w = fmaxf(mx.w, leaky(as.w + ad.w));
    }
#pragma unroll
    for (int o = 16; o; o >>= 1) {
        mx.x = fmaxf(mx.x, __shfl_xor_sync(FULLMASK, mx.x, o));
        mx.y = fmaxf(mx.y, __shfl_xor_sync(FULLMASK, mx.y, o));
        mx.z = fmaxf(mx.z, __shfl_xor_sync(FULLMASK, mx.z, o));
        mx.w = fmaxf(mx.w, __shfl_xor_sync(FULLMASK, mx.w, o));
    }

    // phase 2: exp-sum
    float4 sm = make_float4(0.f, 0.f, 0.f, 0.f);
    for (int j = beg + lane; j < end; j += 32) {
        int s = csrc[j];
        float4 as = *(const float4*)(asrc + s * 4);
        sm.x += __expf(leaky(as.x + ad.x) - mx.x);
        sm.y += __expf(leaky(as.y + ad.y) - mx.y);
        sm.z += __expf(leaky(as.z + ad.z) - mx.z);
        sm.w += __expf(leaky(as.w + ad.w) - mx.w);
    }
#pragma unroll
    for (int o = 16; o; o >>= 1) {
        sm.x += __shfl_xor_sync(FULLMASK, sm.x, o);
        sm.y += __shfl_xor_sync(FULLMASK, sm.y, o);
        sm.z += __shfl_xor_sync(FULLMASK, sm.z, o);
        sm.w += __shfl_xor_sync(FULLMASK, sm.w, o);
    }
    float4 inv = make_float4(1.f / (sm.x + 1e-16f), 1.f / (sm.y + 1e-16f),
                             1.f / (sm.z + 1e-16f), 1.f / (sm.w + 1e-16f));
    float mh = sel4(mx, hsel), ih = sel4(inv, hsel), adh = sel4(ad, hsel);

    // phase 3: weighted gather-accumulate (whole warp walks each edge)
    acc0 = make_float4(0.f, 0.f, 0.f, 0.f);
    acc1 = make_float4(0.f, 0.f, 0.f, 0.f);
    const int cbase = lane * 8;
    for (int j = beg; j < end; j++) {
        int s = csrc[j];
        float as = asrc[s * 4 + hsel];
        float alpha = __expf(leaky(as + adh) - mh) * ih;
        const float4* hp = (const float4*)(hbuf + (size_t)s * HC + cbase);
        float4 v0 = hp[0], v1 = hp[1];
        acc0.x = fmaf(v0.x, alpha, acc0.x);
        acc0.y = fmaf(v0.y, alpha, acc0.y);
        acc0.z = fmaf(v0.z, alpha, acc0.z);
        acc0.w = fmaf(v0.w, alpha, acc0.w);
        acc1.x = fmaf(v1.x, alpha, acc1.x);
        acc1.y = fmaf(v1.y, alpha, acc1.y);
        acc1.z = fmaf(v1.z, alpha, acc1.z);
        acc1.w = fmaf(v1.w, alpha, acc1.w);
    }
}

// layer 1: concat=True epilogue (bias + relu -> [N,256])
__global__ __launch_bounds__(256) void agg1_kernel(const float* __restrict__ hbuf,
                                                   const float* __restrict__ asrc,
                                                   const float* __restrict__ adst,
                                                   const int* __restrict__ rowptr,
                                                   const int* __restrict__ csrc,
                                                   const float* __restrict__ bias,
                                                   float* __restrict__ outbuf, int N) {
    int gw = (blockIdx.x * blockDim.x + threadIdx.x) >> 5;
    int lane = threadIdx.x & 31;
    if (gw >= N) return;
    float4 acc0, acc1;
    agg_core(hbuf, asrc, adst, rowptr, csrc, gw, lane, acc0, acc1);
    int cbase = lane * 8;
    float4 b0 = *(const float4*)(bias + cbase);
    float4 b1 = *(const float4*)(bias + cbase + 4);
    float* op = outbuf + (size_t)gw * HC + cbase;
    ((float4*)op)[0] = make_float4(fmaxf(acc0.x + b0.x, 0.f), fmaxf(acc0.y + b0.y, 0.f),
                                   fmaxf(acc0.z + b0.z, 0.f), fmaxf(acc0.w + b0.w, 0.f));
    ((float4*)op)[1] = make_float4(fmaxf(acc1.x + b1.x, 0.f), fmaxf(acc1.y + b1.y, 0.f),
                                   fmaxf(acc1.z + b1.z, 0.f), fmaxf(acc1.w + b1.w, 0.f));
}

// layer 2: head-mean + bias + relu + softmax(64) -> [N,64]
__global__ __launch_bounds__(256) void agg2_kernel(const float* __restrict__ hbuf,
                                                   const float* __restrict__ asrc,
                                                   const float* __restrict__ adst,
                                                   const int* __restrict__ rowptr,
                                                   const int* __restrict__ csrc,
                                                   const float* __restrict__ bias,
                                                   float* __restrict__ outp, int N) {
    int gw = (blockIdx.x * blockDim.x + threadIdx.x) >> 5;
    int lane = threadIdx.x & 31;
    if (gw >= N) return;
    float4 acc0, acc1;
    agg_core(hbuf, asrc, adst, rowptr, csrc, gw, lane, acc0, acc1);

    float r[8] = {acc0.x, acc0.y, acc0.z, acc0.w, acc1.x, acc1.y, acc1.z, acc1.w};
#pragma unroll
    for (int k = 0; k < 8; k++) {
        r[k] += __shfl_xor_sync(FULLMASK, r[k], 8);
        r[k] += __shfl_xor_sync(FULLMASK, r[k], 16);
    }
    int cp = (lane & 7) * 8;
    float4 b0 = *(const float4*)(bias + cp);
    float4 b1 = *(const float4*)(bias + cp + 4);
    float bb[8] = {b0.x, b0.y, b0.z, b0.w, b1.x, b1.y, b1.z, b1.w};
    float lm = -1e30f;
#pragma unroll
    for (int k = 0; k < 8; k++) {
        r[k] = fmaxf(0.25f * r[k] + bb[k], 0.f);
        lm = fmaxf(lm, r[k]);
    }
#pragma unroll
    for (int o = 4; o; o >>= 1) lm = fmaxf(lm, __shfl_xor_sync(FULLMASK, lm, o));
    float ls = 0.f;
#pragma unroll
    for (int k = 0; k < 8; k++) { r[k] = __expf(r[k] - lm); ls += r[k]; }
#pragma unroll
    for (int o = 4; o; o >>= 1) ls += __shfl_xor_sync(FULLMASK, ls, o);
    float invs = 1.f / ls;
    if (lane < 8) {
        float* op = outp + (size_t)gw * CH + lane * 8;
        ((float4*)op)[0] = make_float4(r[0] * invs, r[1] * invs, r[2] * invs, r[3] * invs);
        ((float4*)op)[1] = make_float4(r[4] * invs, r[5] * invs, r[6] * invs, r[7] * invs);
    }
}

// ---------------- launch -----------------------------------------------------
extern "C" void kernel_launch(void* const* d_in, const int* in_sizes, int n_in,
                              void* d_out, int out_size) {
    const float* x   = (const float*)d_in[0];
    const int*   ei  = (const int*)d_in[1];
    const float* W1  = (const float*)d_in[2];
    const float* as1 = (const float*)d_in[3];
    const float* ad1 = (const float*)d_in[4];
    const float* b1  = (const float*)d_in[5];
    const float* W2  = (const float*)d_in[6];
    const float* as2 = (const float*)d_in[7];
    const float* ad2 = (const float*)d_in[8];
    const float* b2  = (const float*)d_in[9];
    float* out = (float*)d_out;

    const int N = in_sizes[0] / DIN;
    const int E = in_sizes[1] / 2;

    float *dH, *dAct, *dAs, *dAd;
    int *dRow, *dDeg, *dCur, *dCsr;
    cudaGetSymbolAddress((void**)&dH, g_h);
    cudaGetSymbolAddress((void**)&dAct, g_act);
    cudaGetSymbolAddress((void**)&dAs, g_asrc);
    cudaGetSymbolAddress((void**)&dAd, g_adst);
    cudaGetSymbolAddress((void**)&dRow, g_rowptr);
    cudaGetSymbolAddress((void**)&dDeg, g_deg);
    cudaGetSymbolAddress((void**)&dCur, g_cursor);
    cudaGetSymbolAddress((void**)&dCsr, g_csrc);

    cudaFuncSetAttribute(gemm_tf32_kernel,
                         cudaFuncAttributeMaxDynamicSharedMemorySize, GEMM_SMEM);

    // CSR build (by destination node)
    zero2_kernel<<<(N + 255) / 256, 256>>>(dDeg, dCur, N);
    hist_kernel<<<(E + 255) / 256, 256>>>(ei, E, dDeg);
    scan_kernel<<<1, 1024>>>(dDeg, dRow, N);
    scatter_kernel<<<(E + 255) / 256, 256>>>(ei, E, dRow, dCur, dCsr);

    const int warpBlocks = (N * 32 + 255) / 256;
    dim3 gg((N + 127) / 128, HC / 128);

    // layer 1
    gemm_tf32_kernel<<<gg, 256, GEMM_SMEM>>>(x, W1, dH, N, DIN, HC);
    att_kernel<<<warpBlocks, 256>>>(dH, as1, ad1, dAs, dAd, N);
    agg1_kernel<<<warpBlocks, 256>>>(dH, dAs, dAd, dRow, dCsr, b1, dAct, N);

    // layer 2
    gemm_tf32_kernel<<<gg, 256, GEMM_SMEM>>>(dAct, W2, dH, N, HC, HC);
    att_kernel<<<warpBlocks, 256>>>(dH, as2, ad2, dAs, dAd, N);
    agg2_kernel<<<warpBlocks, 256>>>(dH, dAs, dAd, dRow, dCsr, b2, out, N);
}

// round 4
// speedup vs baseline: 1.8945x; 1.0800x over previous
#include <cuda_runtime.h>

#define FULLMASK 0xffffffffu
#define DIN   128
#define HC    256
#define NHEAD 4
#define CH    64
#define NMAX  50016
#define EMAX  900000

// ---------------- scratch (device globals; no allocation allowed) -----------
__device__ float g_h[(size_t)NMAX * HC];    // GEMM output / layer-2 features
__device__ float g_act[(size_t)NMAX * HC];  // layer-1 activations
__device__ float g_asrc[NMAX * NHEAD];
__device__ float g_adst[NMAX * NHEAD];
__device__ int   g_rowptr[NMAX + 1];
__device__ int   g_deg[NMAX];
__device__ int   g_cursor[NMAX];
__device__ int   g_csrc[EMAX];

// ---------------- helpers ---------------------------------------------------
static __device__ __forceinline__ float leaky(float x) { return fmaxf(x, 0.2f * x); }
static __device__ __forceinline__ float sel4(float4 v, int h) {
    return h == 0 ? v.x : (h == 1 ? v.y : (h == 2 ? v.z : v.w));
}

// tf32 split: v = hi + lo, hi = round-to-tf32(v), lo exact fp32 residual
static __device__ __forceinline__ void tfsplit(float v, unsigned& hi, unsigned& lo) {
    unsigned h;
    asm("cvt.rna.tf32.f32 %0, %1;" : "=r"(h) : "f"(v));
    hi = h;
    lo = __float_as_uint(v - __uint_as_float(h));
}

static __device__ __forceinline__ void mma8(float* d, const unsigned* a,
                                            unsigned b0, unsigned b1) {
    asm volatile(
        "mma.sync.aligned.m16n8k8.row.col.f32.tf32.tf32.f32 "
        "{%0,%1,%2,%3},{%4,%5,%6,%7},{%8,%9},{%0,%1,%2,%3};"
        : "+f"(d[0]), "+f"(d[1]), "+f"(d[2]), "+f"(d[3])
        : "r"(a[0]), "r"(a[1]), "r"(a[2]), "r"(a[3]), "r"(b0), "r"(b1));
}

// ---------------- CSR build --------------------------------------------------
__global__ void zero2_kernel(int* a, int* b, int n) {
    int i = blockIdx.x * blockDim.x + threadIdx.x;
    if (i < n) { a[i] = 0; b[i] = 0; }
}

__global__ void hist_kernel(const int* __restrict__ ei, int E, int* __restrict__ deg) {
    int i = blockIdx.x * blockDim.x + threadIdx.x;
    if (i < E) atomicAdd(&deg[ei[E + i]], 1);
}

__global__ void scan_kernel(const int* __restrict__ deg, int* __restrict__ rowptr, int n) {
    __shared__ int partials[1024];
    int tid = threadIdx.x;
    int per = (n + 1023) >> 10;
    int start = tid * per;
    int end = min(start + per, n);
    int s = 0;
    for (int i = start; i < end; i++) s += deg[i];
    partials[tid] = s;
    __syncthreads();
    for (int d = 1; d < 1024; d <<= 1) {
        int v = (tid >= d) ? partials[tid - d] : 0;
        __syncthreads();
        partials[tid] += v;
        __syncthreads();
    }
    int run = partials[tid] - s;  // exclusive prefix
    for (int i = start; i < end; i++) { rowptr[i] = run; run += deg[i]; }
    if (end == n) rowptr[n] = run;
}

__global__ void scatter_kernel(const int* __restrict__ ei, int E,
                               const int* __restrict__ rowptr,
                               int* __restrict__ cursor, int* __restrict__ csrc) {
    int i = blockIdx.x * blockDim.x + threadIdx.x;
    if (i < E) {
        int d = ei[E + i];
        int pos = atomicAdd(&cursor[d], 1);
        csrc[rowptr[d] + pos] = ei[i];
    }
}

// ---------------- tf32 split GEMM + fused attention epilogue -----------------
// C[M,Nn] = A[M,K] @ B[K,Nn]; BM=128, BN=128, BK=32; 8 warps (4m x 2n).
// Epilogue also computes asrc/adst head dot-products (one head per n-warp).
#define A_STRIDE 36
#define B_STRIDE 136
#define A_TILE   (128 * A_STRIDE)
#define B_TILE   (32 * B_STRIDE)
#define GEMM_SMEM ((2 * (A_TILE + B_TILE)) * 4)

__global__ __launch_bounds__(256) void gemm_tf32_kernel(
    const float* __restrict__ A, const float* __restrict__ B,
    float* __restrict__ C,
    const float* __restrict__ attS, const float* __restrict__ attD,
    float* __restrict__ asrc, float* __restrict__ adst,
    int M, int K, int Nn) {
    extern __shared__ float sm[];
    float* Abuf = sm;
    float* Bbuf = sm + 2 * A_TILE;

    const int t = threadIdx.x;
    const int lane = t & 31;
    const int warpid = t >> 5;
    const int wm = warpid & 3;
    const int wn = warpid >> 2;
    const int m0 = blockIdx.x * 128;
    const int n0 = blockIdx.y * 128;
    const int g = lane >> 2, q = lane & 3;

    float acc[2][8][4];
#pragma unroll
    for (int mi = 0; mi < 2; mi++)
#pragma unroll
        for (int ni = 0; ni < 8; ni++)
#pragma unroll
            for (int w = 0; w < 4; w++) acc[mi][ni][w] = 0.f;

    const int ntiles = K >> 5;

    auto issue = [&](int tile, int stage) {
        const int kt = tile << 5;
        float* Ad = Abuf + stage * A_TILE;
        float* Bd = Bbuf + stage * B_TILE;
#pragma unroll
        for (int i = 0; i < 4; i++) {
            int idx = i * 256 + t;
            int m = idx >> 3, kq = idx & 7;
            bool valid = (m0 + m) < M;
            const float* src = A + (size_t)(valid ? (m0 + m) : 0) * K + kt + kq * 4;
            unsigned dst = (unsigned)__cvta_generic_to_shared(Ad + m * A_STRIDE + kq * 4);
            int sz = valid ? 16 : 0;
            asm volatile("cp.async.ca.shared.global [%0], [%1], 16, %2;"
                         :: "r"(dst), "l"(src), "r"(sz));
        }
#pragma unroll
        for (int i = 0; i < 4; i++) {
            int idx = i * 256 + t;
            int r = idx >> 5, cq = idx & 31;
            const float* src = B + (size_t)(kt + r) * Nn + n0 + cq * 4;
            unsigned dst = (unsigned)__cvta_generic_to_shared(Bd + r * B_STRIDE + cq * 4);
            asm volatile("cp.async.ca.shared.global [%0], [%1], 16;"
                         :: "r"(dst), "l"(src));
        }
        asm volatile("cp.async.commit_group;");
    };

    issue(0, 0);

    for (int tile = 0; tile < ntiles; tile++) {
        const int cur = tile & 1;
        if (tile + 1 < ntiles) {
            issue(tile + 1, cur ^ 1);
            asm volatile("cp.async.wait_group 1;");
        } else {
            asm volatile("cp.async.wait_group 0;");
        }
        __syncthreads();
        const float* As = Abuf + cur * A_TILE;
        const float* Bs = Bbuf + cur * B_TILE;

#pragma unroll
        for (int k8 = 0; k8 < 4; k8++) {
            const int kk = k8 * 8;
            unsigned ah[2][4], al[2][4];
#pragma unroll
            for (int mi = 0; mi < 2; mi++) {
                int rb = (wm * 32 + mi * 16 + g) * A_STRIDE + kk + q;
                float x0 = As[rb];
                float x1 = As[rb + 8 * A_STRIDE];
                float x2 = As[rb + 4];
                float x3 = As[rb + 8 * A_STRIDE + 4];
                tfsplit(x0, ah[mi][0], al[mi][0]);
                tfsplit(x1, ah[mi][1], al[mi][1]);
                tfsplit(x2, ah[mi][2], al[mi][2]);
                tfsplit(x3, ah[mi][3], al[mi][3]);
            }
#pragma unroll
            for (int ni = 0; ni < 8; ni++) {
                int cb = (kk + q) * B_STRIDE + wn * 64 + ni * 8 + g;
                float y0 = Bs[cb];
                float y1 = Bs[cb + 4 * B_STRIDE];
                unsigned bh0, bl0, bh1, bl1;
                tfsplit(y0, bh0, bl0);
                tfsplit(y1, bh1, bl1);
#pragma unroll
                for (int mi = 0; mi < 2; mi++) {
                    mma8(acc[mi][ni], ah[mi], bh0, bh1);
                    mma8(acc[mi][ni], ah[mi], bl0, bl1);
                    mma8(acc[mi][ni], al[mi], bh0, bh1);
                }
            }
        }
        __syncthreads();
    }

    // epilogue: store C + fused per-head attention dot products.
    // This block's n-warp covers columns [n0+wn*64, +64) == one full head.
    const int head = blockIdx.y * 2 + wn;
    float2 sS[8], sD[8];
#pragma unroll
    for (int ni = 0; ni < 8; ni++) {
        sS[ni] = *(const float2*)(attS + n0 + wn * 64 + ni * 8 + q * 2);
        sD[ni] = *(const float2*)(attD + n0 + wn * 64 + ni * 8 + q * 2);
    }

#pragma unroll
    for (int mi = 0; mi < 2; mi++) {
        int r0 = m0 + wm * 32 + mi * 16 + g;
        float ps0 = 0.f, pd0 = 0.f, ps1 = 0.f, pd1 = 0.f;
#pragma unroll
        for (int ni = 0; ni < 8; ni++) {
            int cc = n0 + wn * 64 + ni * 8 + q * 2;
            if (r0 < M)
                *(float2*)(C + (size_t)r0 * Nn + cc) =
                    make_float2(acc[mi][ni][0], acc[mi][ni][1]);
            if (r0 + 8 < M)
                *(float2*)(C + (size_t)(r0 + 8) * Nn + cc) =
                    make_float2(acc[mi][ni][2], acc[mi][ni][3]);
            ps0 += acc[mi][ni][0] * sS[ni].x + acc[mi][ni][1] * sS[ni].y;
            pd0 += acc[mi][ni][0] * sD[ni].x + acc[mi][ni][1] * sD[ni].y;
            ps1 += acc[mi][ni][2] * sS[ni].x + acc[mi][ni][3] * sS[ni].y;
            pd1 += acc[mi][ni][2] * sD[ni].x + acc[mi][ni][3] * sD[ni].y;
        }
#pragma unroll
        for (int o = 1; o < 4; o <<= 1) {
            ps0 += __shfl_xor_sync(FULLMASK, ps0, o);
            pd0 += __shfl_xor_sync(FULLMASK, pd0, o);
            ps1 += __shfl_xor_sync(FULLMASK, ps1, o);
            pd1 += __shfl_xor_sync(FULLMASK, pd1, o);
        }
        if (q == 0) {
            if (r0 < M) {
                asrc[r0 * 4 + head] = ps0;
                adst[r0 * 4 + head] = pd0;
            }
            if (r0 + 8 < M) {
                asrc[(r0 + 8) * 4 + head] = ps1;
                adst[(r0 + 8) * 4 + head] = pd1;
            }
        }
    }
}

// ---------------- per-node aggregation core (phases 1-3) ---------------------
static __device__ __forceinline__ void agg_core(const float* __restrict__ hbuf,
                                                const float* __restrict__ asrc,
                                                const float* __restrict__ adst,
                                                const int* __restrict__ rowptr,
                                                const int* __restrict__ csrc,
                                                int gw, int lane,
                                                float4& acc0, float4& acc1) {
    int hsel = lane >> 3;
    int beg = rowptr[gw], end = rowptr[gw + 1];
    float4 ad = *(const float4*)(adst + gw * 4);

    // phase 1: segment max (per head)
    float4 mx = make_float4(-1e30f, -1e30f, -1e30f, -1e30f);
    for (int j = beg + lane; j < end; j += 32) {
        int s = csrc[j];
        float4 as = *(const float4*)(asrc + s * 4);
        mx.x = fmaxf(mx.x, leaky(as.x + ad.x));
        mx.y = fmaxf(mx.y, leaky(as.y + ad.y));
        mx.z = fmaxf(mx.z, leaky(as.z + ad.z));
        mx.w = fmaxf(mx.w, leaky(as.w + ad.w));
    }
#pragma unroll
    for (int o = 16; o; o >>= 1) {
        mx.x = fmaxf(mx.x, __shfl_xor_sync(FULLMASK, mx.x, o));
        mx.y = fmaxf(mx.y, __shfl_xor_sync(FULLMASK, mx.y, o));
        mx.z = fmaxf(mx.z, __shfl_xor_sync(FULLMASK, mx.z, o));
        mx.w = fmaxf(mx.w, __shfl_xor_sync(FULLMASK, mx.w, o));
    }

    // phase 2: exp-sum
    float4 sm = make_float4(0.f, 0.f, 0.f, 0.f);
    for (int j = beg + lane; j < end; j += 32) {
        int s = csrc[j];
        float4 as = *(const float4*)(asrc + s * 4);
        sm.x += __expf(leaky(as.x + ad.x) - mx.x);
        sm.y += __expf(leaky(as.y + ad.y) - mx.y);
        sm.z += __expf(leaky(as.z + ad.z) - mx.z);
        sm.w += __expf(leaky(as.w + ad.w) - mx.w);
    }
#pragma unroll
    for (int o = 16; o; o >>= 1) {
        sm.x += __shfl_xor_sync(FULLMASK, sm.x, o);
        sm.y += __shfl_xor_sync(FULLMASK, sm.y, o);
        sm.z += __shfl_xor_sync(FULLMASK, sm.z, o);
        sm.w += __shfl_xor_sync(FULLMASK, sm.w, o);
    }
    float4 inv = make_float4(1.f / (sm.x + 1e-16f), 1.f / (sm.y + 1e-16f),
                             1.f / (sm.z + 1e-16f), 1.f / (sm.w + 1e-16f));
    float mh = sel4(mx, hsel), ih = sel4(inv, hsel), adh = sel4(ad, hsel);

    // phase 3: weighted gather-accumulate (whole warp walks each edge)
    acc0 = make_float4(0.f, 0.f, 0.f, 0.f);
    acc1 = make_float4(0.f, 0.f, 0.f, 0.f);
    const int cbase = lane * 8;
    for (int j = beg; j < end; j++) {
        int s = csrc[j];
        float as = asrc[s * 4 + hsel];
        float alpha = __expf(leaky(as + adh) - mh) * ih;
        const float4* hp = (const float4*)(hbuf + (size_t)s * HC + cbase);
        float4 v0 = hp[0], v1 = hp[1];
        acc0.x = fmaf(v0.x, alpha, acc0.x);
        acc0.y = fmaf(v0.y, alpha, acc0.y);
        acc0.z = fmaf(v0.z, alpha, acc0.z);
        acc0.w = fmaf(v0.w, alpha, acc0.w);
        acc1.x = fmaf(v1.x, alpha, acc1.x);
        acc1.y = fmaf(v1.y, alpha, acc1.y);
        acc1.z = fmaf(v1.z, alpha, acc1.z);
        acc1.w = fmaf(v1.w, alpha, acc1.w);
    }
}

// layer 1: concat=True epilogue (bias + relu -> [N,256])
__global__ __launch_bounds__(256) void agg1_kernel(const float* __restrict__ hbuf,
                                                   const float* __restrict__ asrc,
                                                   const float* __restrict__ adst,
                                                   const int* __restrict__ rowptr,
                                                   const int* __restrict__ csrc,
                                                   const float* __restrict__ bias,
                                                   float* __restrict__ outbuf, int N) {
    int gw = (blockIdx.x * blockDim.x + threadIdx.x) >> 5;
    int lane = threadIdx.x & 31;
    if (gw >= N) return;
    float4 acc0, acc1;
    agg_core(hbuf, asrc, adst, rowptr, csrc, gw, lane, acc0, acc1);
    int cbase = lane * 8;
    float4 b0 = *(const float4*)(bias + cbase);
    float4 b1 = *(const float4*)(bias + cbase + 4);
    float* op = outbuf + (size_t)gw * HC + cbase;
    ((float4*)op)[0] = make_float4(fmaxf(acc0.x + b0.x, 0.f), fmaxf(acc0.y + b0.y, 0.f),
                                   fmaxf(acc0.z + b0.z, 0.f), fmaxf(acc0.w + b0.w, 0.f));
    ((float4*)op)[1] = make_float4(fmaxf(acc1.x + b1.x, 0.f), fmaxf(acc1.y + b1.y, 0.f),
                                   fmaxf(acc1.z + b1.z, 0.f), fmaxf(acc1.w + b1.w, 0.f));
}

// layer 2: head-mean + bias + relu + softmax(64) -> [N,64]
__global__ __launch_bounds__(256) void agg2_kernel(const float* __restrict__ hbuf,
                                                   const float* __restrict__ asrc,
                                                   const float* __restrict__ adst,
                                                   const int* __restrict__ rowptr,
                                                   const int* __restrict__ csrc,
                                                   const float* __restrict__ bias,
                                                   float* __restrict__ outp, int N) {
    int gw = (blockIdx.x * blockDim.x + threadIdx.x) >> 5;
    int lane = threadIdx.x & 31;
    if (gw >= N) return;
    float4 acc0, acc1;
    agg_core(hbuf, asrc, adst, rowptr, csrc, gw, lane, acc0, acc1);

    float r[8] = {acc0.x, acc0.y, acc0.z, acc0.w, acc1.x, acc1.y, acc1.z, acc1.w};
#pragma unroll
    for (int k = 0; k < 8; k++) {
        r[k] += __shfl_xor_sync(FULLMASK, r[k], 8);
        r[k] += __shfl_xor_sync(FULLMASK, r[k], 16);
    }
    int cp = (lane & 7) * 8;
    float4 b0 = *(const float4*)(bias + cp);
    float4 b1 = *(const float4*)(bias + cp + 4);
    float bb[8] = {b0.x, b0.y, b0.z, b0.w, b1.x, b1.y, b1.z, b1.w};
    float lm = -1e30f;
#pragma unroll
    for (int k = 0; k < 8; k++) {
        r[k] = fmaxf(0.25f * r[k] + bb[k], 0.f);
        lm = fmaxf(lm, r[k]);
    }
#pragma unroll
    for (int o = 4; o; o >>= 1) lm = fmaxf(lm, __shfl_xor_sync(FULLMASK, lm, o));
    float ls = 0.f;
#pragma unroll
    for (int k = 0; k < 8; k++) { r[k] = __expf(r[k] - lm); ls += r[k]; }
#pragma unroll
    for (int o = 4; o; o >>= 1) ls += __shfl_xor_sync(FULLMASK, ls, o);
    float invs = 1.f / ls;
    if (lane < 8) {
        float* op = outp + (size_t)gw * CH + lane * 8;
        ((float4*)op)[0] = make_float4(r[0] * invs, r[1] * invs, r[2] * invs, r[3] * invs);
        ((float4*)op)[1] = make_float4(r[4] * invs, r[5] * invs, r[6] * invs, r[7] * invs);
    }
}

// ---------------- launch -----------------------------------------------------
extern "C" void kernel_launch(void* const* d_in, const int* in_sizes, int n_in,
                              void* d_out, int out_size) {
    const float* x   = (const float*)d_in[0];
    const int*   ei  = (const int*)d_in[1];
    const float* W1  = (const float*)d_in[2];
    const float* as1 = (const float*)d_in[3];
    const float* ad1 = (const float*)d_in[4];
    const float* b1  = (const float*)d_in[5];
    const float* W2  = (const float*)d_in[6];
    const float* as2 = (const float*)d_in[7];
    const float* ad2 = (const float*)d_in[8];
    const float* b2  = (const float*)d_in[9];
    float* out = (float*)d_out;

    const int N = in_sizes[0] / DIN;
    const int E = in_sizes[1] / 2;

    float *dH, *dAct, *dAs, *dAd;
    int *dRow, *dDeg, *dCur, *dCsr;
    cudaGetSymbolAddress((void**)&dH, g_h);
    cudaGetSymbolAddress((void**)&dAct, g_act);
    cudaGetSymbolAddress((void**)&dAs, g_asrc);
    cudaGetSymbolAddress((void**)&dAd, g_adst);
    cudaGetSymbolAddress((void**)&dRow, g_rowptr);
    cudaGetSymbolAddress((void**)&dDeg, g_deg);
    cudaGetSymbolAddress((void**)&dCur, g_cursor);
    cudaGetSymbolAddress((void**)&dCsr, g_csrc);

    cudaFuncSetAttribute(gemm_tf32_kernel,
                         cudaFuncAttributeMaxDynamicSharedMemorySize, GEMM_SMEM);

    // side stream + events, created once on the first (correctness) call,
    // outside graph capture; reused verbatim on the capture call.
    static cudaStream_t s2 = [] { cudaStream_t s; cudaStreamCreate(&s); return s; }();
    static cudaEvent_t evFork = [] {
        cudaEvent_t e; cudaEventCreateWithFlags(&e, cudaEventDisableTiming); return e; }();
    static cudaEvent_t evJoin = [] {
        cudaEvent_t e; cudaEventCreateWithFlags(&e, cudaEventDisableTiming); return e; }();

    const int warpBlocks = (N * 32 + 255) / 256;
    dim3 gg((N + 127) / 128, HC / 128);

    // fork: CSR build on s2, concurrent with GEMM1 on the main stream
    cudaEventRecord(evFork, 0);
    cudaStreamWaitEvent(s2, evFork, 0);

    zero2_kernel<<<(N + 255) / 256, 256, 0, s2>>>(dDeg, dCur, N);
    hist_kernel<<<(E + 255) / 256, 256, 0, s2>>>(ei, E, dDeg);
    scan_kernel<<<1, 1024, 0, s2>>>(dDeg, dRow, N);
    scatter_kernel<<<(E + 255) / 256, 256, 0, s2>>>(ei, E, dRow, dCur, dCsr);
    cudaEventRecord(evJoin, s2);

    // layer 1 GEMM (+ fused attention coefficients) on main stream
    gemm_tf32_kernel<<<gg, 256, GEMM_SMEM>>>(x, W1, dH, as1, ad1, dAs, dAd, N, DIN, HC);

    // join: aggregation needs the CSR
    cudaStreamWaitEvent(0, evJoin, 0);
    agg1_kernel<<<warpBlocks, 256>>>(dH, dAs, dAd, dRow, dCsr, b1, dAct, N);

    // layer 2
    gemm_tf32_kernel<<<gg, 256, GEMM_SMEM>>>(dAct, W2, dH, as2, ad2, dAs, dAd, N, HC, HC);
    agg2_kernel<<<warpBlocks, 256>>>(dH, dAs, dAd, dRow, dCsr, b2, out, N);
}

// round 5
// speedup vs baseline: 2.5120x; 1.3259x over previous
#include <cuda_runtime.h>
#include <cuda_fp16.h>

#define FULLMASK 0xffffffffu
#define DIN   128
#define HC    256
#define NHEAD 4
#define CH    64
#define NMAX  50016
#define EMAX  900000

// ---------------- scratch (device globals; no allocation allowed) -----------
__device__ __half g_h[(size_t)NMAX * HC];   // GEMM output (fp16, gather-only)
__device__ float  g_act[(size_t)NMAX * HC]; // layer-1 activations (fp32, GEMM2 input)
__device__ float  g_asrc[NMAX * NHEAD];
__device__ float  g_adst[NMAX * NHEAD];
__device__ int    g_rowptr[NMAX + 1];
__device__ int    g_deg[NMAX];
__device__ int    g_cursor[NMAX];
__device__ int    g_csrc[EMAX];

// ---------------- helpers ---------------------------------------------------
static __device__ __forceinline__ float leaky(float x) { return fmaxf(x, 0.2f * x); }
static __device__ __forceinline__ float sel4(float4 v, int h) {
    return h == 0 ? v.x : (h == 1 ? v.y : (h == 2 ? v.z : v.w));
}

// bf16 split of a k-adjacent float pair: e0 = even-k elem (low half), e1 = odd-k.
// h = packed bf16x2 of (e0,e1); l = packed bf16x2 of exact residuals.
static __device__ __forceinline__ void bsplit2(float e0, float e1,
                                               unsigned& h, unsigned& l) {
    unsigned hp;
    asm("cvt.rn.bf16x2.f32 %0, %1, %2;" : "=r"(hp) : "f"(e1), "f"(e0));
    float f0 = __uint_as_float(hp << 16);
    float f1 = __uint_as_float(hp & 0xFFFF0000u);
    float r0 = e0 - f0;
    float r1 = e1 - f1;
    asm("cvt.rn.bf16x2.f32 %0, %1, %2;" : "=r"(l) : "f"(r1), "f"(r0));
    h = hp;
}

static __device__ __forceinline__ void mma16(float* d, const unsigned* a,
                                             unsigned b0, unsigned b1) {
    asm volatile(
        "mma.sync.aligned.m16n8k16.row.col.f32.bf16.bf16.f32 "
        "{%0,%1,%2,%3},{%4,%5,%6,%7},{%8,%9},{%0,%1,%2,%3};"
        : "+f"(d[0]), "+f"(d[1]), "+f"(d[2]), "+f"(d[3])
        : "r"(a[0]), "r"(a[1]), "r"(a[2]), "r"(a[3]), "r"(b0), "r"(b1));
}

// ---------------- CSR build --------------------------------------------------
__global__ void zero2_kernel(int* a, int* b, int n) {
    int i = blockIdx.x * blockDim.x + threadIdx.x;
    if (i < n) { a[i] = 0; b[i] = 0; }
}

__global__ void hist_kernel(const int* __restrict__ ei, int E, int* __restrict__ deg) {
    int i = blockIdx.x * blockDim.x + threadIdx.x;
    if (i < E) atomicAdd(&deg[ei[E + i]], 1);
}

__global__ void scan_kernel(const int* __restrict__ deg, int* __restrict__ rowptr, int n) {
    __shared__ int partials[1024];
    int tid = threadIdx.x;
    int per = (n + 1023) >> 10;
    int start = tid * per;
    int end = min(start + per, n);
    int s = 0;
    for (int i = start; i < end; i++) s += deg[i];
    partials[tid] = s;
    __syncthreads();
    for (int d = 1; d < 1024; d <<= 1) {
        int v = (tid >= d) ? partials[tid - d] : 0;
        __syncthreads();
        partials[tid] += v;
        __syncthreads();
    }
    int run = partials[tid] - s;  // exclusive prefix
    for (int i = start; i < end; i++) { rowptr[i] = run; run += deg[i]; }
    if (end == n) rowptr[n] = run;
}

__global__ void scatter_kernel(const int* __restrict__ ei, int E,
                               const int* __restrict__ rowptr,
                               int* __restrict__ cursor, int* __restrict__ csrc) {
    int i = blockIdx.x * blockDim.x + threadIdx.x;
    if (i < E) {
        int d = ei[E + i];
        int pos = atomicAdd(&cursor[d], 1);
        csrc[rowptr[d] + pos] = ei[i];
    }
}

// ---------------- bf16x3 split GEMM + fused attention epilogue ---------------
// C[M,Nn] (fp16 out) = A[M,K] @ B[K,Nn]; BM=128, BN=128, BK=32; 8 warps (4m x 2n).
#define A_STRIDE 36
#define B_STRIDE 132
#define A_TILE   (128 * A_STRIDE)   // 4608 floats
#define B_TILE   (32 * B_STRIDE)    // 4224 floats
#define GEMM_SMEM ((2 * (A_TILE + B_TILE)) * 4)  // 70656 bytes

__global__ __launch_bounds__(256) void gemm_bf16_kernel(
    const float* __restrict__ A, const float* __restrict__ B,
    __half* __restrict__ C,
    const float* __restrict__ attS, const float* __restrict__ attD,
    float* __restrict__ asrc, float* __restrict__ adst,
    int M, int K, int Nn) {
    extern __shared__ float sm[];
    float* Abuf = sm;
    float* Bbuf = sm + 2 * A_TILE;

    const int t = threadIdx.x;
    const int lane = t & 31;
    const int warpid = t >> 5;
    const int wm = warpid & 3;
    const int wn = warpid >> 2;
    const int m0 = blockIdx.x * 128;
    const int n0 = blockIdx.y * 128;
    const int g = lane >> 2, q = lane & 3;

    float acc[2][8][4];
#pragma unroll
    for (int mi = 0; mi < 2; mi++)
#pragma unroll
        for (int ni = 0; ni < 8; ni++)
#pragma unroll
            for (int w = 0; w < 4; w++) acc[mi][ni][w] = 0.f;

    const int ntiles = K >> 5;

    auto issue = [&](int tile, int stage) {
        const int kt = tile << 5;
        float* Ad = Abuf + stage * A_TILE;
        float* Bd = Bbuf + stage * B_TILE;
#pragma unroll
        for (int i = 0; i < 4; i++) {
            int idx = i * 256 + t;
            int m = idx >> 3, kq = idx & 7;
            bool valid = (m0 + m) < M;
            const float* src = A + (size_t)(valid ? (m0 + m) : 0) * K + kt + kq * 4;
            unsigned dst = (unsigned)__cvta_generic_to_shared(Ad + m * A_STRIDE + kq * 4);
            int sz = valid ? 16 : 0;
            asm volatile("cp.async.ca.shared.global [%0], [%1], 16, %2;"
                         :: "r"(dst), "l"(src), "r"(sz));
        }
#pragma unroll
        for (int i = 0; i < 4; i++) {
            int idx = i * 256 + t;
            int r = idx >> 5, cq = idx & 31;
            const float* src = B + (size_t)(kt + r) * Nn + n0 + cq * 4;
            unsigned dst = (unsigned)__cvta_generic_to_shared(Bd + r * B_STRIDE + cq * 4);
            asm volatile("cp.async.ca.shared.global [%0], [%1], 16;"
                         :: "r"(dst), "l"(src));
        }
        asm volatile("cp.async.commit_group;");
    };

    issue(0, 0);

    for (int tile = 0; tile < ntiles; tile++) {
        const int cur = tile & 1;
        if (tile + 1 < ntiles) {
            issue(tile + 1, cur ^ 1);
            asm volatile("cp.async.wait_group 1;");
        } else {
            asm volatile("cp.async.wait_group 0;");
        }
        __syncthreads();
        const float* As = Abuf + cur * A_TILE;
        const float* Bs = Bbuf + cur * B_TILE;

#pragma unroll
        for (int k16 = 0; k16 < 2; k16++) {
            const int kk = k16 * 16;
            unsigned ah[2][4], al[2][4];
#pragma unroll
            for (int mi = 0; mi < 2; mi++) {
                int r0 = wm * 32 + mi * 16 + g;
                float2 p00 = *(const float2*)(As + r0 * A_STRIDE + kk + 2 * q);
                float2 p10 = *(const float2*)(As + (r0 + 8) * A_STRIDE + kk + 2 * q);
                float2 p01 = *(const float2*)(As + r0 * A_STRIDE + kk + 2 * q + 8);
                float2 p11 = *(const float2*)(As + (r0 + 8) * A_STRIDE + kk + 2 * q + 8);
                bsplit2(p00.x, p00.y, ah[mi][0], al[mi][0]);
                bsplit2(p10.x, p10.y, ah[mi][1], al[mi][1]);
                bsplit2(p01.x, p01.y, ah[mi][2], al[mi][2]);
                bsplit2(p11.x, p11.y, ah[mi][3], al[mi][3]);
            }
#pragma unroll
            for (int ni = 0; ni < 8; ni++) {
                int nb = wn * 64 + ni * 8 + g;
                float e0 = Bs[(kk + 2 * q) * B_STRIDE + nb];
                float e1 = Bs[(kk + 2 * q + 1) * B_STRIDE + nb];
                float e2 = Bs[(kk + 2 * q + 8) * B_STRIDE + nb];
                float e3 = Bs[(kk + 2 * q + 9) * B_STRIDE + nb];
                unsigned bh0, bl0, bh1, bl1;
                bsplit2(e0, e1, bh0, bl0);
                bsplit2(e2, e3, bh1, bl1);
#pragma unroll
                for (int mi = 0; mi < 2; mi++) {
                    mma16(acc[mi][ni], ah[mi], bh0, bh1);
                    mma16(acc[mi][ni], ah[mi], bl0, bl1);
                    mma16(acc[mi][ni], al[mi], bh0, bh1);
                }
            }
        }
        __syncthreads();
    }

    // epilogue: store C (fp16) + fused per-head attention dot products (fp32 accs).
    const int head = blockIdx.y * 2 + wn;
    float2 sS[8], sD[8];
#pragma unroll
    for (int ni = 0; ni < 8; ni++) {
        sS[ni] = *(const float2*)(attS + n0 + wn * 64 + ni * 8 + q * 2);
        sD[ni] = *(const float2*)(attD + n0 + wn * 64 + ni * 8 + q * 2);
    }

#pragma unroll
    for (int mi = 0; mi < 2; mi++) {
        int r0 = m0 + wm * 32 + mi * 16 + g;
        float ps0 = 0.f, pd0 = 0.f, ps1 = 0.f, pd1 = 0.f;
#pragma unroll
        for (int ni = 0; ni < 8; ni++) {
            int cc = n0 + wn * 64 + ni * 8 + q * 2;
            if (r0 < M)
                *(__half2*)(C + (size_t)r0 * Nn + cc) =
                    __floats2half2_rn(acc[mi][ni][0], acc[mi][ni][1]);
            if (r0 + 8 < M)
                *(__half2*)(C + (size_t)(r0 + 8) * Nn + cc) =
                    __floats2half2_rn(acc[mi][ni][2], acc[mi][ni][3]);
            ps0 += acc[mi][ni][0] * sS[ni].x + acc[mi][ni][1] * sS[ni].y;
            pd0 += acc[mi][ni][0] * sD[ni].x + acc[mi][ni][1] * sD[ni].y;
            ps1 += acc[mi][ni][2] * sS[ni].x + acc[mi][ni][3] * sS[ni].y;
            pd1 += acc[mi][ni][2] * sD[ni].x + acc[mi][ni][3] * sD[ni].y;
        }
#pragma unroll
        for (int o = 1; o < 4; o <<= 1) {
            ps0 += __shfl_xor_sync(FULLMASK, ps0, o);
            pd0 += __shfl_xor_sync(FULLMASK, pd0, o);
            ps1 += __shfl_xor_sync(FULLMASK, ps1, o);
            pd1 += __shfl_xor_sync(FULLMASK, pd1, o);
        }
        if (q == 0) {
            if (r0 < M) {
                asrc[r0 * 4 + head] = ps0;
                adst[r0 * 4 + head] = pd0;
            }
            if (r0 + 8 < M) {
                asrc[(r0 + 8) * 4 + head] = ps1;
                adst[(r0 + 8) * 4 + head] = pd1;
            }
        }
    }
}

// ---------------- per-node aggregation core (phases 1-3) ---------------------
static __device__ __forceinline__ void agg_core(const __half* __restrict__ hbuf,
                                                const float* __restrict__ asrc,
                                                const float* __restrict__ adst,
                                                const int* __restrict__ rowptr,
                                                const int* __restrict__ csrc,
                                                int gw, int lane,
                                                float4& acc0, float4& acc1) {
    int hsel = lane >> 3;
    int beg = rowptr[gw], end = rowptr[gw + 1];
    float4 ad = *(const float4*)(adst + gw * 4);

    // phase 1: segment max (per head)
    float4 mx = make_float4(-1e30f, -1e30f, -1e30f, -1e30f);
    for (int j = beg + lane; j < end; j += 32) {
        int s = csrc[j];
        float4 as = *(const float4*)(asrc + s * 4);
        mx.x = fmaxf(mx.x, leaky(as.x + ad.x));
        mx.y = fmaxf(mx.y, leaky(as.y + ad.y));
        mx.z = fmaxf(mx.z, leaky(as.z + ad.z));
        mx.w = fmaxf(mx.w, leaky(as.w + ad.w));
    }
#pragma unroll
    for (int o = 16; o; o >>= 1) {
        mx.x = fmaxf(mx.x, __shfl_xor_sync(FULLMASK, mx.x, o));
        mx.y = fmaxf(mx.y, __shfl_xor_sync(FULLMASK, mx.y, o));
        mx.z = fmaxf(mx.z, __shfl_xor_sync(FULLMASK, mx.z, o));
        mx.w = fmaxf(mx.w, __shfl_xor_sync(FULLMASK, mx.w, o));
    }

    // phase 2: exp-sum
    float4 sm = make_float4(0.f, 0.f, 0.f, 0.f);
    for (int j = beg + lane; j < end; j += 32) {
        int s = csrc[j];
        float4 as = *(const float4*)(asrc + s * 4);
        sm.x += __expf(leaky(as.x + ad.x) - mx.x);
        sm.y += __expf(leaky(as.y + ad.y) - mx.y);
        sm.z += __expf(leaky(as.z + ad.z) - mx.z);
        sm.w += __expf(leaky(as.w + ad.w) - mx.w);
    }
#pragma unroll
    for (int o = 16; o; o >>= 1) {
        sm.x += __shfl_xor_sync(FULLMASK, sm.x, o);
        sm.y += __shfl_xor_sync(FULLMASK, sm.y, o);
        sm.z += __shfl_xor_sync(FULLMASK, sm.z, o);
        sm.w += __shfl_xor_sync(FULLMASK, sm.w, o);
    }
    float4 inv = make_float4(1.f / (sm.x + 1e-16f), 1.f / (sm.y + 1e-16f),
                             1.f / (sm.z + 1e-16f), 1.f / (sm.w + 1e-16f));
    float mh = sel4(mx, hsel), ih = sel4(inv, hsel), adh = sel4(ad, hsel);

    // phase 3: weighted gather-accumulate (whole warp walks each edge; fp16 h)
    acc0 = make_float4(0.f, 0.f, 0.f, 0.f);
    acc1 = make_float4(0.f, 0.f, 0.f, 0.f);
    const int cbase = lane * 8;
    for (int j = beg; j < end; j++) {
        int s = csrc[j];
        float as = asrc[s * 4 + hsel];
        float alpha = __expf(leaky(as + adh) - mh) * ih;
        union { uint4 u; __half2 h2[4]; } uu;
        uu.u = *(const uint4*)(hbuf + (size_t)s * HC + cbase);
        float2 f0 = __half22float2(uu.h2[0]);
        float2 f1 = __half22float2(uu.h2[1]);
        float2 f2 = __half22float2(uu.h2[2]);
        float2 f3 = __half22float2(uu.h2[3]);
        acc0.x = fmaf(f0.x, alpha, acc0.x);
        acc0.y = fmaf(f0.y, alpha, acc0.y);
        acc0.z = fmaf(f1.x, alpha, acc0.z);
        acc0.w = fmaf(f1.y, alpha, acc0.w);
        acc1.x = fmaf(f2.x, alpha, acc1.x);
        acc1.y = fmaf(f2.y, alpha, acc1.y);
        acc1.z = fmaf(f3.x, alpha, acc1.z);
        acc1.w = fmaf(f3.y, alpha, acc1.w);
    }
}

// layer 1: concat=True epilogue (bias + relu -> [N,256] fp32)
__global__ __launch_bounds__(256) void agg1_kernel(const __half* __restrict__ hbuf,
                                                   const float* __restrict__ asrc,
                                                   const float* __restrict__ adst,
                                                   const int* __restrict__ rowptr,
                                                   const int* __restrict__ csrc,
                                                   const float* __restrict__ bias,
                                                   float* __restrict__ outbuf, int N) {
    int gw = (blockIdx.x * blockDim.x + threadIdx.x) >> 5;
    int lane = threadIdx.x & 31;
    if (gw >= N) return;
    float4 acc0, acc1;
    agg_core(hbuf, asrc, adst, rowptr, csrc, gw, lane, acc0, acc1);
    int cbase = lane * 8;
    float4 b0 = *(const float4*)(bias + cbase);
    float4 b1 = *(const float4*)(bias + cbase + 4);
    float* op = outbuf + (size_t)gw * HC + cbase;
    ((float4*)op)[0] = make_float4(fmaxf(acc0.x + b0.x, 0.f), fmaxf(acc0.y + b0.y, 0.f),
                                   fmaxf(acc0.z + b0.z, 0.f), fmaxf(acc0.w + b0.w, 0.f));
    ((float4*)op)[1] = make_float4(fmaxf(acc1.x + b1.x, 0.f), fmaxf(acc1.y + b1.y, 0.f),
                                   fmaxf(acc1.z + b1.z, 0.f), fmaxf(acc1.w + b1.w, 0.f));
}

// layer 2: head-mean + bias + relu + softmax(64) -> [N,64]
__global__ __launch_bounds__(256) void agg2_kernel(const __half* __restrict__ hbuf,
                                                   const float* __restrict__ asrc,
                                                   const float* __restrict__ adst,
                                                   const int* __restrict__ rowptr,
                                                   const int* __restrict__ csrc,
                                                   const float* __restrict__ bias,
                                                   float* __restrict__ outp, int N) {
    int gw = (blockIdx.x * blockDim.x + threadIdx.x) >> 5;
    int lane = threadIdx.x & 31;
    if (gw >= N) return;
    float4 acc0, acc1;
    agg_core(hbuf, asrc, adst, rowptr, csrc, gw, lane, acc0, acc1);

    float r[8] = {acc0.x, acc0.y, acc0.z, acc0.w, acc1.x, acc1.y, acc1.z, acc1.w};
#pragma unroll
    for (int k = 0; k < 8; k++) {
        r[k] += __shfl_xor_sync(FULLMASK, r[k], 8);
        r[k] += __shfl_xor_sync(FULLMASK, r[k], 16);
    }
    int cp = (lane & 7) * 8;
    float4 b0 = *(const float4*)(bias + cp);
    float4 b1 = *(const float4*)(bias + cp + 4);
    float bb[8] = {b0.x, b0.y, b0.z, b0.w, b1.x, b1.y, b1.z, b1.w};
    float lm = -1e30f;
#pragma unroll
    for (int k = 0; k < 8; k++) {
        r[k] = fmaxf(0.25f * r[k] + bb[k], 0.f);
        lm = fmaxf(lm, r[k]);
    }
#pragma unroll
    for (int o = 4; o; o >>= 1) lm = fmaxf(lm, __shfl_xor_sync(FULLMASK, lm, o));
    float ls = 0.f;
#pragma unroll
    for (int k = 0; k < 8; k++) { r[k] = __expf(r[k] - lm); ls += r[k]; }
#pragma unroll
    for (int o = 4; o; o >>= 1) ls += __shfl_xor_sync(FULLMASK, ls, o);
    float invs = 1.f / ls;
    if (lane < 8) {
        float* op = outp + (size_t)gw * CH + lane * 8;
        ((float4*)op)[0] = make_float4(r[0] * invs, r[1] * invs, r[2] * invs, r[3] * invs);
        ((float4*)op)[1] = make_float4(r[4] * invs, r[5] * invs, r[6] * invs, r[7] * invs);
    }
}

// ---------------- launch -----------------------------------------------------
extern "C" void kernel_launch(void* const* d_in, const int* in_sizes, int n_in,
                              void* d_out, int out_size) {
    const float* x   = (const float*)d_in[0];
    const int*   ei  = (const int*)d_in[1];
    const float* W1  = (const float*)d_in[2];
    const float* as1 = (const float*)d_in[3];
    const float* ad1 = (const float*)d_in[4];
    const float* b1  = (const float*)d_in[5];
    const float* W2  = (const float*)d_in[6];
    const float* as2 = (const float*)d_in[7];
    const float* ad2 = (const float*)d_in[8];
    const float* b2  = (const float*)d_in[9];
    float* out = (float*)d_out;

    const int N = in_sizes[0] / DIN;
    const int E = in_sizes[1] / 2;

    __half* dH;
    float *dAct, *dAs, *dAd;
    int *dRow, *dDeg, *dCur, *dCsr;
    cudaGetSymbolAddress((void**)&dH, g_h);
    cudaGetSymbolAddress((void**)&dAct, g_act);
    cudaGetSymbolAddress((void**)&dAs, g_asrc);
    cudaGetSymbolAddress((void**)&dAd, g_adst);
    cudaGetSymbolAddress((void**)&dRow, g_rowptr);
    cudaGetSymbolAddress((void**)&dDeg, g_deg);
    cudaGetSymbolAddress((void**)&dCur, g_cursor);
    cudaGetSymbolAddress((void**)&dCsr, g_csrc);

    cudaFuncSetAttribute(gemm_bf16_kernel,
                         cudaFuncAttributeMaxDynamicSharedMemorySize, GEMM_SMEM);

    // side stream + events, created once on the first (correctness) call,
    // outside graph capture; reused verbatim on the capture call.
    static cudaStream_t s2 = [] { cudaStream_t s; cudaStreamCreate(&s); return s; }();
    static cudaEvent_t evFork = [] {
        cudaEvent_t e; cudaEventCreateWithFlags(&e, cudaEventDisableTiming); return e; }();
    static cudaEvent_t evJoin = [] {
        cudaEvent_t e; cudaEventCreateWithFlags(&e, cudaEventDisableTiming); return e; }();

    const int warpBlocks = (N * 32 + 255) / 256;
    dim3 gg((N + 127) / 128, HC / 128);

    // fork: CSR build on s2, concurrent with GEMM1 on the main stream
    cudaEventRecord(evFork, 0);
    cudaStreamWaitEvent(s2, evFork, 0);

    zero2_kernel<<<(N + 255) / 256, 256, 0, s2>>>(dDeg, dCur, N);
    hist_kernel<<<(E + 255) / 256, 256, 0, s2>>>(ei, E, dDeg);
    scan_kernel<<<1, 1024, 0, s2>>>(dDeg, dRow, N);
    scatter_kernel<<<(E + 255) / 256, 256, 0, s2>>>(ei, E, dRow, dCur, dCsr);
    cudaEventRecord(evJoin, s2);

    // layer 1 GEMM (+ fused attention coefficients) on main stream
    gemm_bf16_kernel<<<gg, 256, GEMM_SMEM>>>(x, W1, dH, as1, ad1, dAs, dAd, N, DIN, HC);

    // join: aggregation needs the CSR
    cudaStreamWaitEvent(0, evJoin, 0);
    agg1_kernel<<<warpBlocks, 256>>>(dH, dAs, dAd, dRow, dCsr, b1, dAct, N);

    // layer 2
    gemm_bf16_kernel<<<gg, 256, GEMM_SMEM>>>(dAct, W2, dH, as2, ad2, dAs, dAd, N, HC, HC);
    agg2_kernel<<<warpBlocks, 256>>>(dH, dAs, dAd, dRow, dCsr, b2, out, N);
}

// round 6
// speedup vs baseline: 2.7379x; 1.0899x over previous
#include <cuda_runtime.h>
#include <cuda_fp16.h>

#define FULLMASK 0xffffffffu
#define DIN   128
#define HC    256
#define NHEAD 4
#define CH    64
#define NMAX  50016
#define EMAX  900000

// ---------------- scratch (device globals; no allocation allowed) -----------
__device__ __half g_h[(size_t)NMAX * HC];   // GEMM output (fp16, gather-only)
__device__ float  g_act[(size_t)NMAX * HC]; // layer-1 activations (fp32, GEMM2 input)
__device__ float  g_asrc[NMAX * NHEAD];
__device__ float  g_adst[NMAX * NHEAD];
__device__ int    g_rowptr[NMAX + 1];
__device__ int    g_deg[NMAX];
__device__ int    g_cursor[NMAX];
__device__ int    g_csrc[EMAX];

// ---------------- helpers ---------------------------------------------------
static __device__ __forceinline__ float leaky(float x) { return fmaxf(x, 0.2f * x); }
static __device__ __forceinline__ float sel4(float4 v, int h) {
    return h == 0 ? v.x : (h == 1 ? v.y : (h == 2 ? v.z : v.w));
}

// pack two floats into f16x2 (e0 -> low half, e1 -> high half)
static __device__ __forceinline__ unsigned packh2(float e0, float e1) {
    unsigned r;
    asm("cvt.rn.f16x2.f32 %0, %1, %2;" : "=r"(r) : "f"(e1), "f"(e0));
    return r;
}
// exact fp16 split of a float pair: h = fp16x2 round, l = fp16x2 of residuals
static __device__ __forceinline__ void fsplit2(float e0, float e1,
                                               unsigned& h, unsigned& l) {
    unsigned hp = packh2(e0, e1);
    __half2 hh = *reinterpret_cast<__half2*>(&hp);
    float2 f = __half22float2(hh);
    l = packh2(e0 - f.x, e1 - f.y);
    h = hp;
}

static __device__ __forceinline__ void mma16f(float* d, const unsigned* a,
                                              unsigned b0, unsigned b1) {
    asm volatile(
        "mma.sync.aligned.m16n8k16.row.col.f32.f16.f16.f32 "
        "{%0,%1,%2,%3},{%4,%5,%6,%7},{%8,%9},{%0,%1,%2,%3};"
        : "+f"(d[0]), "+f"(d[1]), "+f"(d[2]), "+f"(d[3])
        : "r"(a[0]), "r"(a[1]), "r"(a[2]), "r"(a[3]), "r"(b0), "r"(b1));
}

// ---------------- CSR build --------------------------------------------------
__global__ void zero2_kernel(int* a, int* b, int n) {
    int i = blockIdx.x * blockDim.x + threadIdx.x;
    if (i < n) { a[i] = 0; b[i] = 0; }
}

__global__ void hist_kernel(const int* __restrict__ ei, int E, int* __restrict__ deg) {
    int i = blockIdx.x * blockDim.x + threadIdx.x;
    if (i < E) atomicAdd(&deg[ei[E + i]], 1);
}

__global__ void scan_kernel(const int* __restrict__ deg, int* __restrict__ rowptr, int n) {
    __shared__ int partials[1024];
    int tid = threadIdx.x;
    int per = (n + 1023) >> 10;
    int start = tid * per;
    int end = min(start + per, n);
    int s = 0;
    for (int i = start; i < end; i++) s += deg[i];
    partials[tid] = s;
    __syncthreads();
    for (int d = 1; d < 1024; d <<= 1) {
        int v = (tid >= d) ? partials[tid - d] : 0;
        __syncthreads();
        partials[tid] += v;
        __syncthreads();
    }
    int run = partials[tid] - s;  // exclusive prefix
    for (int i = start; i < end; i++) { rowptr[i] = run; run += deg[i]; }
    if (end == n) rowptr[n] = run;
}

__global__ void scatter_kernel(const int* __restrict__ ei, int E,
                               const int* __restrict__ rowptr,
                               int* __restrict__ cursor, int* __restrict__ csrc) {
    int i = blockIdx.x * blockDim.x + threadIdx.x;
    if (i < E) {
        int d = ei[E + i];
        int pos = atomicAdd(&cursor[d], 1);
        csrc[rowptr[d] + pos] = ei[i];
    }
}

// ---------------- fp16 2-term GEMM + fused attention epilogue ----------------
// D = (Ah + Al) @ round16(B); BM=128, BN=128, BK=32; 8 warps (4m x 2n).
#define A_STRIDE 36
#define B_STRIDE 132
#define A_TILE   (128 * A_STRIDE)   // 4608 floats
#define B_TILE   (32 * B_STRIDE)    // 4224 floats
#define GEMM_SMEM ((2 * (A_TILE + B_TILE)) * 4)  // 70656 bytes

__global__ __launch_bounds__(256) void gemm_f16_kernel(
    const float* __restrict__ A, const float* __restrict__ B,
    __half* __restrict__ C,
    const float* __restrict__ attS, const float* __restrict__ attD,
    float* __restrict__ asrc, float* __restrict__ adst,
    int M, int K, int Nn) {
    extern __shared__ float sm[];
    float* Abuf = sm;
    float* Bbuf = sm + 2 * A_TILE;

    const int t = threadIdx.x;
    const int lane = t & 31;
    const int warpid = t >> 5;
    const int wm = warpid & 3;
    const int wn = warpid >> 2;
    const int m0 = blockIdx.x * 128;
    const int n0 = blockIdx.y * 128;
    const int g = lane >> 2, q = lane & 3;

    float acc[2][8][4];
#pragma unroll
    for (int mi = 0; mi < 2; mi++)
#pragma unroll
        for (int ni = 0; ni < 8; ni++)
#pragma unroll
            for (int w = 0; w < 4; w++) acc[mi][ni][w] = 0.f;

    const int ntiles = K >> 5;

    auto issue = [&](int tile, int stage) {
        const int kt = tile << 5;
        float* Ad = Abuf + stage * A_TILE;
        float* Bd = Bbuf + stage * B_TILE;
#pragma unroll
        for (int i = 0; i < 4; i++) {
            int idx = i * 256 + t;
            int m = idx >> 3, kq = idx & 7;
            bool valid = (m0 + m) < M;
            const float* src = A + (size_t)(valid ? (m0 + m) : 0) * K + kt + kq * 4;
            unsigned dst = (unsigned)__cvta_generic_to_shared(Ad + m * A_STRIDE + kq * 4);
            int sz = valid ? 16 : 0;
            asm volatile("cp.async.ca.shared.global [%0], [%1], 16, %2;"
                         :: "r"(dst), "l"(src), "r"(sz));
        }
#pragma unroll
        for (int i = 0; i < 4; i++) {
            int idx = i * 256 + t;
            int r = idx >> 5, cq = idx & 31;
            const float* src = B + (size_t)(kt + r) * Nn + n0 + cq * 4;
            unsigned dst = (unsigned)__cvta_generic_to_shared(Bd + r * B_STRIDE + cq * 4);
            asm volatile("cp.async.ca.shared.global [%0], [%1], 16;"
                         :: "r"(dst), "l"(src));
        }
        asm volatile("cp.async.commit_group;");
    };

    issue(0, 0);

    for (int tile = 0; tile < ntiles; tile++) {
        const int cur = tile & 1;
        if (tile + 1 < ntiles) {
            issue(tile + 1, cur ^ 1);
            asm volatile("cp.async.wait_group 1;");
        } else {
            asm volatile("cp.async.wait_group 0;");
        }
        __syncthreads();
        const float* As = Abuf + cur * A_TILE;
        const float* Bs = Bbuf + cur * B_TILE;

#pragma unroll
        for (int k16 = 0; k16 < 2; k16++) {
            const int kk = k16 * 16;
            unsigned ah[2][4], al[2][4];
#pragma unroll
            for (int mi = 0; mi < 2; mi++) {
                int r0 = wm * 32 + mi * 16 + g;
                float2 p00 = *(const float2*)(As + r0 * A_STRIDE + kk + 2 * q);
                float2 p10 = *(const float2*)(As + (r0 + 8) * A_STRIDE + kk + 2 * q);
                float2 p01 = *(const float2*)(As + r0 * A_STRIDE + kk + 2 * q + 8);
                float2 p11 = *(const float2*)(As + (r0 + 8) * A_STRIDE + kk + 2 * q + 8);
                fsplit2(p00.x, p00.y, ah[mi][0], al[mi][0]);
                fsplit2(p10.x, p10.y, ah[mi][1], al[mi][1]);
                fsplit2(p01.x, p01.y, ah[mi][2], al[mi][2]);
                fsplit2(p11.x, p11.y, ah[mi][3], al[mi][3]);
            }
#pragma unroll
            for (int ni = 0; ni < 8; ni++) {
                int nb = wn * 64 + ni * 8 + g;
                float e0 = Bs[(kk + 2 * q) * B_STRIDE + nb];
                float e1 = Bs[(kk + 2 * q + 1) * B_STRIDE + nb];
                float e2 = Bs[(kk + 2 * q + 8) * B_STRIDE + nb];
                float e3 = Bs[(kk + 2 * q + 9) * B_STRIDE + nb];
                unsigned b0 = packh2(e0, e1);
                unsigned b1 = packh2(e2, e3);
#pragma unroll
                for (int mi = 0; mi < 2; mi++) {
                    mma16f(acc[mi][ni], ah[mi], b0, b1);
                    mma16f(acc[mi][ni], al[mi], b0, b1);
                }
            }
        }
        __syncthreads();
    }

    // epilogue: store C (fp16) + fused per-head attention dot products (fp32 accs).
    const int head = blockIdx.y * 2 + wn;
    float2 sS[8], sD[8];
#pragma unroll
    for (int ni = 0; ni < 8; ni++) {
        sS[ni] = *(const float2*)(attS + n0 + wn * 64 + ni * 8 + q * 2);
        sD[ni] = *(const float2*)(attD + n0 + wn * 64 + ni * 8 + q * 2);
    }

#pragma unroll
    for (int mi = 0; mi < 2; mi++) {
        int r0 = m0 + wm * 32 + mi * 16 + g;
        float ps0 = 0.f, pd0 = 0.f, ps1 = 0.f, pd1 = 0.f;
#pragma unroll
        for (int ni = 0; ni < 8; ni++) {
            int cc = n0 + wn * 64 + ni * 8 + q * 2;
            if (r0 < M)
                *(__half2*)(C + (size_t)r0 * Nn + cc) =
                    __floats2half2_rn(acc[mi][ni][0], acc[mi][ni][1]);
            if (r0 + 8 < M)
                *(__half2*)(C + (size_t)(r0 + 8) * Nn + cc) =
                    __floats2half2_rn(acc[mi][ni][2], acc[mi][ni][3]);
            ps0 += acc[mi][ni][0] * sS[ni].x + acc[mi][ni][1] * sS[ni].y;
            pd0 += acc[mi][ni][0] * sD[ni].x + acc[mi][ni][1] * sD[ni].y;
            ps1 += acc[mi][ni][2] * sS[ni].x + acc[mi][ni][3] * sS[ni].y;
            pd1 += acc[mi][ni][2] * sD[ni].x + acc[mi][ni][3] * sD[ni].y;
        }
#pragma unroll
        for (int o = 1; o < 4; o <<= 1) {
            ps0 += __shfl_xor_sync(FULLMASK, ps0, o);
            pd0 += __shfl_xor_sync(FULLMASK, pd0, o);
            ps1 += __shfl_xor_sync(FULLMASK, ps1, o);
            pd1 += __shfl_xor_sync(FULLMASK, pd1, o);
        }
        if (q == 0) {
            if (r0 < M) {
                asrc[r0 * 4 + head] = ps0;
                adst[r0 * 4 + head] = pd0;
            }
            if (r0 + 8 < M) {
                asrc[(r0 + 8) * 4 + head] = ps1;
                adst[(r0 + 8) * 4 + head] = pd1;
            }
        }
    }
}

// ---------------- per-node aggregation core (phases 1-3) ---------------------
static __device__ __forceinline__ void agg_core(const __half* __restrict__ hbuf,
                                                const float* __restrict__ asrc,
                                                const float* __restrict__ adst,
                                                const int* __restrict__ rowptr,
                                                const int* __restrict__ csrc,
                                                int gw, int lane,
                                                float4& acc0, float4& acc1) {
    int hsel = lane >> 3;
    int beg = rowptr[gw], end = rowptr[gw + 1];
    float4 ad = *(const float4*)(adst + gw * 4);

    // phase 1: segment max (per head)
    float4 mx = make_float4(-1e30f, -1e30f, -1e30f, -1e30f);
    for (int j = beg + lane; j < end; j += 32) {
        int s = csrc[j];
        float4 as = *(const float4*)(asrc + s * 4);
        mx.x = fmaxf(mx.x, leaky(as.x + ad.x));
        mx.y = fmaxf(mx.y, leaky(as.y + ad.y));
        mx.z = fmaxf(mx.z, leaky(as.z + ad.z));
        mx.w = fmaxf(mx.w, leaky(as.w + ad.w));
    }
#pragma unroll
    for (int o = 16; o; o >>= 1) {
        mx.x = fmaxf(mx.x, __shfl_xor_sync(FULLMASK, mx.x, o));
        mx.y = fmaxf(mx.y, __shfl_xor_sync(FULLMASK, mx.y, o));
        mx.z = fmaxf(mx.z, __shfl_xor_sync(FULLMASK, mx.z, o));
        mx.w = fmaxf(mx.w, __shfl_xor_sync(FULLMASK, mx.w, o));
    }

    // phase 2: exp-sum
    float4 sm = make_float4(0.f, 0.f, 0.f, 0.f);
    for (int j = beg + lane; j < end; j += 32) {
        int s = csrc[j];
        float4 as = *(const float4*)(asrc + s * 4);
        sm.x += __expf(leaky(as.x + ad.x) - mx.x);
        sm.y += __expf(leaky(as.y + ad.y) - mx.y);
        sm.z += __expf(leaky(as.z + ad.z) - mx.z);
        sm.w += __expf(leaky(as.w + ad.w) - mx.w);
    }
#pragma unroll
    for (int o = 16; o; o >>= 1) {
        sm.x += __shfl_xor_sync(FULLMASK, sm.x, o);
        sm.y += __shfl_xor_sync(FULLMASK, sm.y, o);
        sm.z += __shfl_xor_sync(FULLMASK, sm.z, o);
        sm.w += __shfl_xor_sync(FULLMASK, sm.w, o);
    }
    float4 inv = make_float4(1.f / (sm.x + 1e-16f), 1.f / (sm.y + 1e-16f),
                             1.f / (sm.z + 1e-16f), 1.f / (sm.w + 1e-16f));
    float mh = sel4(mx, hsel), ih = sel4(inv, hsel), adh = sel4(ad, hsel);

    // phase 3: weighted gather-accumulate (whole warp walks each edge; fp16 h)
    acc0 = make_float4(0.f, 0.f, 0.f, 0.f);
    acc1 = make_float4(0.f, 0.f, 0.f, 0.f);
    const int cbase = lane * 8;
    for (int j = beg; j < end; j++) {
        int s = csrc[j];
        float as = asrc[s * 4 + hsel];
        float alpha = __expf(leaky(as + adh) - mh) * ih;
        union { uint4 u; __half2 h2[4]; } uu;
        uu.u = *(const uint4*)(hbuf + (size_t)s * HC + cbase);
        float2 f0 = __half22float2(uu.h2[0]);
        float2 f1 = __half22float2(uu.h2[1]);
        float2 f2 = __half22float2(uu.h2[2]);
        float2 f3 = __half22float2(uu.h2[3]);
        acc0.x = fmaf(f0.x, alpha, acc0.x);
        acc0.y = fmaf(f0.y, alpha, acc0.y);
        acc0.z = fmaf(f1.x, alpha, acc0.z);
        acc0.w = fmaf(f1.y, alpha, acc0.w);
        acc1.x = fmaf(f2.x, alpha, acc1.x);
        acc1.y = fmaf(f2.y, alpha, acc1.y);
        acc1.z = fmaf(f3.x, alpha, acc1.z);
        acc1.w = fmaf(f3.y, alpha, acc1.w);
    }
}

// layer 1: concat=True epilogue (bias + relu -> [N,256] fp32)
__global__ __launch_bounds__(256) void agg1_kernel(const __half* __restrict__ hbuf,
                                                   const float* __restrict__ asrc,
                                                   const float* __restrict__ adst,
                                                   const int* __restrict__ rowptr,
                                                   const int* __restrict__ csrc,
                                                   const float* __restrict__ bias,
                                                   float* __restrict__ outbuf, int N) {
    int gw = (blockIdx.x * blockDim.x + threadIdx.x) >> 5;
    int lane = threadIdx.x & 31;
    if (gw >= N) return;
    float4 acc0, acc1;
    agg_core(hbuf, asrc, adst, rowptr, csrc, gw, lane, acc0, acc1);
    int cbase = lane * 8;
    float4 b0 = *(const float4*)(bias + cbase);
    float4 b1 = *(const float4*)(bias + cbase + 4);
    float* op = outbuf + (size_t)gw * HC + cbase;
    ((float4*)op)[0] = make_float4(fmaxf(acc0.x + b0.x, 0.f), fmaxf(acc0.y + b0.y, 0.f),
                                   fmaxf(acc0.z + b0.z, 0.f), fmaxf(acc0.w + b0.w, 0.f));
    ((float4*)op)[1] = make_float4(fmaxf(acc1.x + b1.x, 0.f), fmaxf(acc1.y + b1.y, 0.f),
                                   fmaxf(acc1.z + b1.z, 0.f), fmaxf(acc1.w + b1.w, 0.f));
}

// layer 2: head-mean + bias + relu + softmax(64) -> [N,64]
__global__ __launch_bounds__(256) void agg2_kernel(const __half* __restrict__ hbuf,
                                                   const float* __restrict__ asrc,
                                                   const float* __restrict__ adst,
                                                   const int* __restrict__ rowptr,
                                                   const int* __restrict__ csrc,
                                                   const float* __restrict__ bias,
                                                   float* __restrict__ outp, int N) {
    int gw = (blockIdx.x * blockDim.x + threadIdx.x) >> 5;
    int lane = threadIdx.x & 31;
    if (gw >= N) return;
    float4 acc0, acc1;
    agg_core(hbuf, asrc, adst, rowptr, csrc, gw, lane, acc0, acc1);

    float r[8] = {acc0.x, acc0.y, acc0.z, acc0.w, acc1.x, acc1.y, acc1.z, acc1.w};
#pragma unroll
    for (int k = 0; k < 8; k++) {
        r[k] += __shfl_xor_sync(FULLMASK, r[k], 8);
        r[k] += __shfl_xor_sync(FULLMASK, r[k], 16);
    }
    int cp = (lane & 7) * 8;
    float4 b0 = *(const float4*)(bias + cp);
    float4 b1 = *(const float4*)(bias + cp + 4);
    float bb[8] = {b0.x, b0.y, b0.z, b0.w, b1.x, b1.y, b1.z, b1.w};
    float lm = -1e30f;
#pragma unroll
    for (int k = 0; k < 8; k++) {
        r[k] = fmaxf(0.25f * r[k] + bb[k], 0.f);
        lm = fmaxf(lm, r[k]);
    }
#pragma unroll
    for (int o = 4; o; o >>= 1) lm = fmaxf(lm, __shfl_xor_sync(FULLMASK, lm, o));
    float ls = 0.f;
#pragma unroll
    for (int k = 0; k < 8; k++) { r[k] = __expf(r[k] - lm); ls += r[k]; }
#pragma unroll
    for (int o = 4; o; o >>= 1) ls += __shfl_xor_sync(FULLMASK, ls, o);
    float invs = 1.f / ls;
    if (lane < 8) {
        float* op = outp + (size_t)gw * CH + lane * 8;
        ((float4*)op)[0] = make_float4(r[0] * invs, r[1] * invs, r[2] * invs, r[3] * invs);
        ((float4*)op)[1] = make_float4(r[4] * invs, r[5] * invs, r[6] * invs, r[7] * invs);
    }
}

// ---------------- launch -----------------------------------------------------
extern "C" void kernel_launch(void* const* d_in, const int* in_sizes, int n_in,
                              void* d_out, int out_size) {
    const float* x   = (const float*)d_in[0];
    const int*   ei  = (const int*)d_in[1];
    const float* W1  = (const float*)d_in[2];
    const float* as1 = (const float*)d_in[3];
    const float* ad1 = (const float*)d_in[4];
    const float* b1  = (const float*)d_in[5];
    const float* W2  = (const float*)d_in[6];
    const float* as2 = (const float*)d_in[7];
    const float* ad2 = (const float*)d_in[8];
    const float* b2  = (const float*)d_in[9];
    float* out = (float*)d_out;

    const int N = in_sizes[0] / DIN;
    const int E = in_sizes[1] / 2;

    __half* dH;
    float *dAct, *dAs, *dAd;
    int *dRow, *dDeg, *dCur, *dCsr;
    cudaGetSymbolAddress((void**)&dH, g_h);
    cudaGetSymbolAddress((void**)&dAct, g_act);
    cudaGetSymbolAddress((void**)&dAs, g_asrc);
    cudaGetSymbolAddress((void**)&dAd, g_adst);
    cudaGetSymbolAddress((void**)&dRow, g_rowptr);
    cudaGetSymbolAddress((void**)&dDeg, g_deg);
    cudaGetSymbolAddress((void**)&dCur, g_cursor);
    cudaGetSymbolAddress((void**)&dCsr, g_csrc);

    cudaFuncSetAttribute(gemm_f16_kernel,
                         cudaFuncAttributeMaxDynamicSharedMemorySize, GEMM_SMEM);

    // side stream + events, created once on the first (correctness) call,
    // outside graph capture; reused verbatim on the capture call.
    static cudaStream_t s2 = [] { cudaStream_t s; cudaStreamCreate(&s); return s; }();
    static cudaEvent_t evFork = [] {
        cudaEvent_t e; cudaEventCreateWithFlags(&e, cudaEventDisableTiming); return e; }();
    static cudaEvent_t evJoin = [] {
        cudaEvent_t e; cudaEventCreateWithFlags(&e, cudaEventDisableTiming); return e; }();

    const int warpBlocks = (N * 32 + 255) / 256;
    dim3 gg((N + 127) / 128, HC / 128);

    // fork: CSR build on s2, concurrent with GEMM1 on the main stream
    cudaEventRecord(evFork, 0);
    cudaStreamWaitEvent(s2, evFork, 0);

    zero2_kernel<<<(N + 255) / 256, 256, 0, s2>>>(dDeg, dCur, N);
    hist_kernel<<<(E + 255) / 256, 256, 0, s2>>>(ei, E, dDeg);
    scan_kernel<<<1, 1024, 0, s2>>>(dDeg, dRow, N);
    scatter_kernel<<<(E + 255) / 256, 256, 0, s2>>>(ei, E, dRow, dCur, dCsr);
    cudaEventRecord(evJoin, s2);

    // layer 1 GEMM (+ fused attention coefficients) on main stream
    gemm_f16_kernel<<<gg, 256, GEMM_SMEM>>>(x, W1, dH, as1, ad1, dAs, dAd, N, DIN, HC);

    // join: aggregation needs the CSR
    cudaStreamWaitEvent(0, evJoin, 0);
    agg1_kernel<<<warpBlocks, 256>>>(dH, dAs, dAd, dRow, dCsr, b1, dAct, N);

    // layer 2
    gemm_f16_kernel<<<gg, 256, GEMM_SMEM>>>(dAct, W2, dH, as2, ad2, dAs, dAd, N, HC, HC);
    agg2_kernel<<<warpBlocks, 256>>>(dH, dAs, dAd, dRow, dCsr, b2, out, N);
}

// round 8
// speedup vs baseline: 3.2260x; 1.1783x over previous
#include <cuda_runtime.h>
#include <cuda_fp16.h>

#define FULLMASK 0xffffffffu
#define DIN   128
#define HC    256
#define NHEAD 4
#define CH    64
#define NMAX  50016
#define EMAX  900000

// ---------------- scratch (device globals; no allocation allowed) -----------
__device__ __half g_h[(size_t)NMAX * HC];     // GEMM output (fp16, gather-only)
__device__ __half g_xh[(size_t)NMAX * DIN];   // x split hi
__device__ __half g_xl[(size_t)NMAX * DIN];   // x split lo
__device__ __half g_acth[(size_t)NMAX * HC];  // act split hi
__device__ __half g_actl[(size_t)NMAX * HC];  // act split lo
__device__ __half g_w1h[DIN * HC];            // W1 rounded to fp16
__device__ __half g_w2h[HC * HC];             // W2 rounded to fp16
__device__ float  g_asrc[NMAX * NHEAD];
__device__ float  g_adst[NMAX * NHEAD];
__device__ int    g_rowptr[NMAX + 1];
__device__ int    g_deg[NMAX];
__device__ int    g_cursor[NMAX];
__device__ int    g_csrc[EMAX];

// ---------------- helpers ---------------------------------------------------
static __device__ __forceinline__ float leaky(float x) { return fmaxf(x, 0.2f * x); }
static __device__ __forceinline__ float sel4(float4 v, int h) {
    return h == 0 ? v.x : (h == 1 ? v.y : (h == 2 ? v.z : v.w));
}
// pack two floats into f16x2 (e0 -> low half, e1 -> high half)
static __device__ __forceinline__ unsigned packh2(float e0, float e1) {
    unsigned r;
    asm("cvt.rn.f16x2.f32 %0, %1, %2;" : "=r"(r) : "f"(e1), "f"(e0));
    return r;
}
static __device__ __forceinline__ float2 unpackh2(unsigned h) {
    __half2 hh = *reinterpret_cast<__half2*>(&h);
    return __half22float2(hh);
}

static __device__ __forceinline__ void mma16f(float* d, const unsigned* a,
                                              unsigned b0, unsigned b1) {
    asm volatile(
        "mma.sync.aligned.m16n8k16.row.col.f32.f16.f16.f32 "
        "{%0,%1,%2,%3},{%4,%5,%6,%7},{%8,%9},{%0,%1,%2,%3};"
        : "+f"(d[0]), "+f"(d[1]), "+f"(d[2]), "+f"(d[3])
        : "r"(a[0]), "r"(a[1]), "r"(a[2]), "r"(a[3]), "r"(b0), "r"(b1));
}
static __device__ __forceinline__ void ldsm_x4(unsigned& r0, unsigned& r1,
                                               unsigned& r2, unsigned& r3, unsigned a) {
    asm volatile("ldmatrix.sync.aligned.m8n8.x4.shared.b16 {%0,%1,%2,%3}, [%4];"
                 : "=r"(r0), "=r"(r1), "=r"(r2), "=r"(r3) : "r"(a));
}
static __device__ __forceinline__ void ldsm_x2t(unsigned& r0, unsigned& r1, unsigned a) {
    asm volatile("ldmatrix.sync.aligned.m8n8.x2.trans.shared.b16 {%0,%1}, [%2];"
                 : "=r"(r0), "=r"(r1) : "r"(a));
}

// ---------------- operand preparation ----------------------------------------
__global__ void split_x_kernel(const float* __restrict__ x,
                               __half* __restrict__ xh, __half* __restrict__ xl,
                               int nquads) {
    int i = blockIdx.x * blockDim.x + threadIdx.x;
    if (i >= nquads) return;
    float4 v = ((const float4*)x)[i];
    unsigned h01 = packh2(v.x, v.y), h23 = packh2(v.z, v.w);
    float2 f01 = unpackh2(h01), f23 = unpackh2(h23);
    unsigned l01 = packh2(v.x - f01.x, v.y - f01.y);
    unsigned l23 = packh2(v.z - f23.x, v.w - f23.y);
    ((uint2*)xh)[i] = make_uint2(h01, h23);
    ((uint2*)xl)[i] = make_uint2(l01, l23);
}

__global__ void round_w_kernel(const float* __restrict__ w, __half* __restrict__ wh,
                               int nquads) {
    int i = blockIdx.x * blockDim.x + threadIdx.x;
    if (i >= nquads) return;
    float4 v = ((const float4*)w)[i];
    ((uint2*)wh)[i] = make_uint2(packh2(v.x, v.y), packh2(v.z, v.w));
}

// ---------------- CSR build --------------------------------------------------
__global__ void zero2_kernel(int* a, int* b, int n) {
    int i = blockIdx.x * blockDim.x + threadIdx.x;
    if (i < n) { a[i] = 0; b[i] = 0; }
}

__global__ void hist_kernel(const int* __restrict__ ei, int E, int* __restrict__ deg) {
    int i = blockIdx.x * blockDim.x + threadIdx.x;
    if (i < E) atomicAdd(&deg[ei[E + i]], 1);
}

__global__ void scan_kernel(const int* __restrict__ deg, int* __restrict__ rowptr, int n) {
    __shared__ int partials[1024];
    int tid = threadIdx.x;
    int per = (n + 1023) >> 10;
    int start = tid * per;
    int end = min(start + per, n);
    int s = 0;
    for (int i = start; i < end; i++) s += deg[i];
    partials[tid] = s;
    __syncthreads();
    for (int d = 1; d < 1024; d <<= 1) {
        int v = (tid >= d) ? partials[tid - d] : 0;
        __syncthreads();
        partials[tid] += v;
        __syncthreads();
    }
    int run = partials[tid] - s;  // exclusive prefix
    for (int i = start; i < end; i++) { rowptr[i] = run; run += deg[i]; }
    if (end == n) rowptr[n] = run;
}

__global__ void scatter_kernel(const int* __restrict__ ei, int E,
                               const int* __restrict__ rowptr,
                               int* __restrict__ cursor, int* __restrict__ csrc) {
    int i = blockIdx.x * blockDim.x + threadIdx.x;
    if (i < E) {
        int d = ei[E + i];
        int pos = atomicAdd(&cursor[d], 1);
        csrc[rowptr[d] + pos] = ei[i];
    }
}

// ---------------- fp16 2-term GEMM (pre-split A, pre-rounded B) --------------
// D = (Ah + Al) @ Bh; BM=128, BN=128, BK=32; 8 warps (4m x 2n); ldmatrix operands.
#define A_ST_H 40     // halves/row (80 B): 8 rows cover 32 banks exactly
#define B_ST_H 136    // halves/row (272 B): same property
#define A_TILE_H (128 * A_ST_H)  // 5120 halves per buffer
#define B_TILE_H (32 * B_ST_H)   // 4352 halves
#define STAGE_BYTES ((2 * A_TILE_H + B_TILE_H) * 2)  // 29184
#define GEMM_SMEM (2 * STAGE_BYTES)                  // 58368

__global__ __launch_bounds__(256) void gemm_f16_kernel(
    const __half* __restrict__ AhG, const __half* __restrict__ AlG,
    const __half* __restrict__ BhG,
    __half* __restrict__ C,
    const float* __restrict__ attS, const float* __restrict__ attD,
    float* __restrict__ asrc, float* __restrict__ adst,
    int M, int K, int Nn) {
    extern __shared__ char smc[];
    const unsigned ubase = (unsigned)__cvta_generic_to_shared(smc);

    const int t = threadIdx.x;
    const int lane = t & 31;
    const int warpid = t >> 5;
    const int wm = warpid & 3;
    const int wn = warpid >> 2;
    const int m0 = blockIdx.x * 128;
    const int n0 = blockIdx.y * 128;
    const int g = lane >> 2, q = lane & 3;

    float acc[2][8][4];
#pragma unroll
    for (int mi = 0; mi < 2; mi++)
#pragma unroll
        for (int ni = 0; ni < 8; ni++)
#pragma unroll
            for (int w = 0; w < 4; w++) acc[mi][ni][w] = 0.f;

    const int ntiles = K >> 5;

    auto issue = [&](int tile, int stage) {
        const int kt = tile << 5;
        unsigned ahB = ubase + stage * STAGE_BYTES;
        unsigned alB = ahB + A_TILE_H * 2;
        unsigned bB  = alB + A_TILE_H * 2;
#pragma unroll
        for (int i = 0; i < 2; i++) {
            int c = i * 256 + t;            // 0..511
            int row = c >> 2, kq = c & 3;   // 4x16B chunks per row
            bool valid = (m0 + row) < M;
            size_t off = (size_t)(valid ? (m0 + row) : 0) * K + kt + kq * 8;
            unsigned d1 = ahB + row * 80 + kq * 16;
            unsigned d2 = alB + row * 80 + kq * 16;
            int sz = valid ? 16 : 0;
            asm volatile("cp.async.ca.shared.global [%0], [%1], 16, %2;"
                         :: "r"(d1), "l"(AhG + off), "r"(sz));
            asm volatile("cp.async.ca.shared.global [%0], [%1], 16, %2;"
                         :: "r"(d2), "l"(AlG + off), "r"(sz));
        }
#pragma unroll
        for (int i = 0; i < 2; i++) {
            int c = i * 256 + t;            // 0..511
            int r = c >> 4, c16 = c & 15;   // 16x16B chunks per row
            const __half* src = BhG + (size_t)(kt + r) * Nn + n0 + c16 * 8;
            unsigned dst = bB + r * 272 + c16 * 16;
            asm volatile("cp.async.ca.shared.global [%0], [%1], 16;"
                         :: "r"(dst), "l"(src));
        }
        asm volatile("cp.async.commit_group;");
    };

    issue(0, 0);

    for (int tile = 0; tile < ntiles; tile++) {
        const int cur = tile & 1;
        if (tile + 1 < ntiles) {
            issue(tile + 1, cur ^ 1);
            asm volatile("cp.async.wait_group 1;");
        } else {
            asm volatile("cp.async.wait_group 0;");
        }
        __syncthreads();
        unsigned ahB = ubase + cur * STAGE_BYTES;
        unsigned alB = ahB + A_TILE_H * 2;
        unsigned bB  = alB + A_TILE_H * 2;

#pragma unroll
        for (int k16 = 0; k16 < 2; k16++) {
            const int kk = k16 * 16;
            unsigned ah[2][4], al[2][4];
#pragma unroll
            for (int mi = 0; mi < 2; mi++) {
                unsigned rowoff = (unsigned)((wm * 32 + mi * 16 + (lane & 15)) * 80 +
                                             (kk + ((lane >> 4) << 3)) * 2);
                ldsm_x4(ah[mi][0], ah[mi][1], ah[mi][2], ah[mi][3], ahB + rowoff);
                ldsm_x4(al[mi][0], al[mi][1], al[mi][2], al[mi][3], alB + rowoff);
            }
#pragma unroll
            for (int ni = 0; ni < 8; ni++) {
                unsigned baddr = bB + (unsigned)((kk + (lane & 15)) * 272 +
                                                 (wn * 64 + ni * 8) * 2);
                unsigned b0, b1;
                ldsm_x2t(b0, b1, baddr);
                mma16f(acc[0][ni], ah[0], b0, b1);
                mma16f(acc[0][ni], al[0], b0, b1);
                mma16f(acc[1][ni], ah[1], b0, b1);
                mma16f(acc[1][ni], al[1], b0, b1);
            }
        }
        __syncthreads();
    }

    // epilogue: store C (fp16) + fused per-head attention dot products (fp32 accs).
    const int head = blockIdx.y * 2 + wn;
    float2 sS[8], sD[8];
#pragma unroll
    for (int ni = 0; ni < 8; ni++) {
        sS[ni] = *(const float2*)(attS + n0 + wn * 64 + ni * 8 + q * 2);
        sD[ni] = *(const float2*)(attD + n0 + wn * 64 + ni * 8 + q * 2);
    }

#pragma unroll
    for (int mi = 0; mi < 2; mi++) {
        int r0 = m0 + wm * 32 + mi * 16 + g;
        float ps0 = 0.f, pd0 = 0.f, ps1 = 0.f, pd1 = 0.f;
#pragma unroll
        for (int ni = 0; ni < 8; ni++) {
            int cc = n0 + wn * 64 + ni * 8 + q * 2;
            if (r0 < M)
                *(__half2*)(C + (size_t)r0 * Nn + cc) =
                    __floats2half2_rn(acc[mi][ni][0], acc[mi][ni][1]);
            if (r0 + 8 < M)
                *(__half2*)(C + (size_t)(r0 + 8) * Nn + cc) =
                    __floats2half2_rn(acc[mi][ni][2], acc[mi][ni][3]);
            ps0 += acc[mi][ni][0] * sS[ni].x + acc[mi][ni][1] * sS[ni].y;
            pd0 += acc[mi][ni][0] * sD[ni].x + acc[mi][ni][1] * sD[ni].y;
            ps1 += acc[mi][ni][2] * sS[ni].x + acc[mi][ni][3] * sS[ni].y;
            pd1 += acc[mi][ni][2] * sD[ni].x + acc[mi][ni][3] * sD[ni].y;
        }
#pragma unroll
        for (int o = 1; o < 4; o <<= 1) {
            ps0 += __shfl_xor_sync(FULLMASK, ps0, o);
            pd0 += __shfl_xor_sync(FULLMASK, pd0, o);
            ps1 += __shfl_xor_sync(FULLMASK, ps1, o);
            pd1 += __shfl_xor_sync(FULLMASK, pd1, o);
        }
        if (q == 0) {
            if (r0 < M) {
                asrc[r0 * 4 + head] = ps0;
                adst[r0 * 4 + head] = pd0;
            }
            if (r0 + 8 < M) {
                asrc[(r0 + 8) * 4 + head] = ps1;
                adst[(r0 + 8) * 4 + head] = pd1;
            }
        }
    }
}

// ---------------- per-node aggregation core (phases 1-3) ---------------------
static __device__ __forceinline__ void agg_core(const __half* __restrict__ hbuf,
                                                const float* __restrict__ asrc,
                                                const float* __restrict__ adst,
                                                const int* __restrict__ rowptr,
                                                const int* __restrict__ csrc,
                                                int gw, int lane,
                                                float4& acc0, float4& acc1) {
    int hsel = lane >> 3;
    int beg = rowptr[gw], end = rowptr[gw + 1];
    float4 ad = *(const float4*)(adst + gw * 4);

    // phase 1: segment max (per head); lanes stride the edge list
    float4 mx = make_float4(-1e30f, -1e30f, -1e30f, -1e30f);
    for (int j = beg + lane; j < end; j += 32) {
        int s = csrc[j];
        float4 as = *(const float4*)(asrc + s * 4);
        mx.x = fmaxf(mx.x, leaky(as.x + ad.x));
        mx.y = fmaxf(mx.y, leaky(as.y + ad.y));
        mx.z = fmaxf(mx.z, leaky(as.z + ad.z));
        mx.w = fmaxf(mx.w, leaky(as.w + ad.w));
    }
#pragma unroll
    for (int o = 16; o; o >>= 1) {
        mx.x = fmaxf(mx.x, __shfl_xor_sync(FULLMASK, mx.x, o));
        mx.y = fmaxf(mx.y, __shfl_xor_sync(FULLMASK, mx.y, o));
        mx.z = fmaxf(mx.z, __shfl_xor_sync(FULLMASK, mx.z, o));
        mx.w = fmaxf(mx.w, __shfl_xor_sync(FULLMASK, mx.w, o));
    }

    // phase 2: exp-sum
    float4 sm = make_float4(0.f, 0.f, 0.f, 0.f);
    for (int j = beg + lane; j < end; j += 32) {
        int s = csrc[j];
        float4 as = *(const float4*)(asrc + s * 4);
        sm.x += __expf(leaky(as.x + ad.x) - mx.x);
        sm.y += __expf(leaky(as.y + ad.y) - mx.y);
        sm.z += __expf(leaky(as.z + ad.z) - mx.z);
        sm.w += __expf(leaky(as.w + ad.w) - mx.w);
    }
#pragma unroll
    for (int o = 16; o; o >>= 1) {
        sm.x += __shfl_xor_sync(FULLMASK, sm.x, o);
        sm.y += __shfl_xor_sync(FULLMASK, sm.y, o);
        sm.z += __shfl_xor_sync(FULLMASK, sm.z, o);
        sm.w += __shfl_xor_sync(FULLMASK, sm.w, o);
    }
    float4 inv = make_float4(1.f / (sm.x + 1e-16f), 1.f / (sm.y + 1e-16f),
                             1.f / (sm.z + 1e-16f), 1.f / (sm.w + 1e-16f));
    float mh = sel4(mx, hsel), ih = sel4(inv, hsel), adh = sel4(ad, hsel);

    // phase 3: weighted gather-accumulate, 2 edges per iteration (MLP x2)
    acc0 = make_float4(0.f, 0.f, 0.f, 0.f);
    acc1 = make_float4(0.f, 0.f, 0.f, 0.f);
    const int cbase = lane * 8;
    int j = beg;
    for (; j + 2 <= end; j += 2) {
        int s0 = csrc[j], s1 = csrc[j + 1];
        float as0 = asrc[s0 * 4 + hsel];
        float as1 = asrc[s1 * 4 + hsel];
        union { uint4 u; __half2 h2[4]; } u0, u1;
        u0.u = *(const uint4*)(hbuf + (size_t)s0 * HC + cbase);
        u1.u = *(const uint4*)(hbuf + (size_t)s1 * HC + cbase);
        float a0 = __expf(leaky(as0 + adh) - mh) * ih;
        float a1 = __expf(leaky(as1 + adh) - mh) * ih;
        float2 p;
        p = __half22float2(u0.h2[0]); acc0.x = fmaf(p.x, a0, acc0.x); acc0.y = fmaf(p.y, a0, acc0.y);
        p = __half22float2(u0.h2[1]); acc0.z = fmaf(p.x, a0, acc0.z); acc0.w = fmaf(p.y, a0, acc0.w);
        p = __half22float2(u0.h2[2]); acc1.x = fmaf(p.x, a0, acc1.x); acc1.y = fmaf(p.y, a0, acc1.y);
        p = __half22float2(u0.h2[3]); acc1.z = fmaf(p.x, a0, acc1.z); acc1.w = fmaf(p.y, a0, acc1.w);
        p = __half22float2(u1.h2[0]); acc0.x = fmaf(p.x, a1, acc0.x); acc0.y = fmaf(p.y, a1, acc0.y);
        p = __half22float2(u1.h2[1]); acc0.z = fmaf(p.x, a1, acc0.z); acc0.w = fmaf(p.y, a1, acc0.w);
        p = __half22float2(u1.h2[2]); acc1.x = fmaf(p.x, a1, acc1.x); acc1.y = fmaf(p.y, a1, acc1.y);
        p = __half22float2(u1.h2[3]); acc1.z = fmaf(p.x, a1, acc1.z); acc1.w = fmaf(p.y, a1, acc1.w);
    }
    if (j < end) {
        int s = csrc[j];
        float as = asrc[s * 4 + hsel];
        float alpha = __expf(leaky(as + adh) - mh) * ih;
        union { uint4 u; __half2 h2[4]; } uu;
        uu.u = *(const uint4*)(hbuf + (size_t)s * HC + cbase);
        float2 p;
        p = __half22float2(uu.h2[0]); acc0.x = fmaf(p.x, alpha, acc0.x); acc0.y = fmaf(p.y, alpha, acc0.y);
        p = __half22float2(uu.h2[1]); acc0.z = fmaf(p.x, alpha, acc0.z); acc0.w = fmaf(p.y, alpha, acc0.w);
        p = __half22float2(uu.h2[2]); acc1.x = fmaf(p.x, alpha, acc1.x); acc1.y = fmaf(p.y, alpha, acc1.y);
        p = __half22float2(uu.h2[3]); acc1.z = fmaf(p.x, alpha, acc1.z); acc1.w = fmaf(p.y, alpha, acc1.w);
    }
}

// layer 1: concat epilogue (bias + relu), emits pre-split fp16 act (hi+lo)
__global__ __launch_bounds__(256) void agg1_kernel(const __half* __restrict__ hbuf,
                                                   const float* __restrict__ asrc,
                                                   const float* __restrict__ adst,
                                                   const int* __restrict__ rowptr,
                                                   const int* __restrict__ csrc,
                                                   const float* __restrict__ bias,
                                                   __half* __restrict__ acth,
                                                   __half* __restrict__ actl, int N) {
    int gw = (blockIdx.x * blockDim.x + threadIdx.x) >> 5;
    int lane = threadIdx.x & 31;
    if (gw >= N) return;
    float4 acc0, acc1;
    agg_core(hbuf, asrc, adst, rowptr, csrc, gw, lane, acc0, acc1);
    int cbase = lane * 8;
    float4 b0 = *(const float4*)(bias + cbase);
    float4 b1 = *(const float4*)(bias + cbase + 4);
    float v[8] = {fmaxf(acc0.x + b0.x, 0.f), fmaxf(acc0.y + b0.y, 0.f),
                  fmaxf(acc0.z + b0.z, 0.f), fmaxf(acc0.w + b0.w, 0.f),
                  fmaxf(acc1.x + b1.x, 0.f), fmaxf(acc1.y + b1.y, 0.f),
                  fmaxf(acc1.z + b1.z, 0.f), fmaxf(acc1.w + b1.w, 0.f)};
    unsigned hh[4], ll[4];
#pragma unroll
    for (int p = 0; p < 4; p++) {
        hh[p] = packh2(v[2 * p], v[2 * p + 1]);
        float2 f = unpackh2(hh[p]);
        ll[p] = packh2(v[2 * p] - f.x, v[2 * p + 1] - f.y);
    }
    *(uint4*)(acth + (size_t)gw * HC + cbase) = make_uint4(hh[0], hh[1], hh[2], hh[3]);
    *(uint4*)(actl + (size_t)gw * HC + cbase) = make_uint4(ll[0], ll[1], ll[2], ll[3]);
}

// layer 2: head-mean + bias + relu + softmax(64) -> [N,64]
__global__ __launch_bounds__(256) void agg2_kernel(const __half* __restrict__ hbuf,
                                                   const float* __restrict__ asrc,
                                                   const float* __restrict__ adst,
                                                   const int* __restrict__ rowptr,
                                                   const int* __restrict__ csrc,
                                                   const float* __restrict__ bias,
                                                   float* __restrict__ outp, int N) {
    int gw = (blockIdx.x * blockDim.x + threadIdx.x) >> 5;
    int lane = threadIdx.x & 31;
    if (gw >= N) return;
    float4 acc0, acc1;
    agg_core(hbuf, asrc, adst, rowptr, csrc, gw, lane, acc0, acc1);

    float r[8] = {acc0.x, acc0.y, acc0.z, acc0.w, acc1.x, acc1.y, acc1.z, acc1.w};
#pragma unroll
    for (int k = 0; k < 8; k++) {
        r[k] += __shfl_xor_sync(FULLMASK, r[k], 8);
        r[k] += __shfl_xor_sync(FULLMASK, r[k], 16);
    }
    int cp = (lane & 7) * 8;
    float4 b0 = *(const float4*)(bias + cp);
    float4 b1 = *(const float4*)(bias + cp + 4);
    float bb[8] = {b0.x, b0.y, b0.z, b0.w, b1.x, b1.y, b1.z, b1.w};
    float lm = -1e30f;
#pragma unroll
    for (int k = 0; k < 8; k++) {
        r[k] = fmaxf(0.25f * r[k] + bb[k], 0.f);
        lm = fmaxf(lm, r[k]);
    }
#pragma unroll
    for (int o = 4; o; o >>= 1) lm = fmaxf(lm, __shfl_xor_sync(FULLMASK, lm, o));
    float ls = 0.f;
#pragma unroll
    for (int k = 0; k < 8; k++) { r[k] = __expf(r[k] - lm); ls += r[k]; }
#pragma unroll
    for (int o = 4; o; o >>= 1) ls += __shfl_xor_sync(FULLMASK, ls, o);
    float invs = 1.f / ls;
    if (lane < 8) {
        float* op = outp + (size_t)gw * CH + lane * 8;
        ((float4*)op)[0] = make_float4(r[0] * invs, r[1] * invs, r[2] * invs, r[3] * invs);
        ((float4*)op)[1] = make_float4(r[4] * invs, r[5] * invs, r[6] * invs, r[7] * invs);
    }
}

// ---------------- launch -----------------------------------------------------
extern "C" void kernel_launch(void* const* d_in, const int* in_sizes, int n_in,
                              void* d_out, int out_size) {
    const float* x   = (const float*)d_in[0];
    const int*   ei  = (const int*)d_in[1];
    const float* W1  = (const float*)d_in[2];
    const float* as1 = (const float*)d_in[3];
    const float* ad1 = (const float*)d_in[4];
    const float* b1  = (const float*)d_in[5];
    const float* W2  = (const float*)d_in[6];
    const float* as2 = (const float*)d_in[7];
    const float* ad2 = (const float*)d_in[8];
    const float* b2  = (const float*)d_in[9];
    float* out = (float*)d_out;

    const int N = in_sizes[0] / DIN;
    const int E = in_sizes[1] / 2;

    __half *dH, *dXh, *dXl, *dAh, *dAl, *dW1h, *dW2h;
    float *dAs, *dAd;
    int *dRow, *dDeg, *dCur, *dCsr;
    cudaGetSymbolAddress((void**)&dH, g_h);
    cudaGetSymbolAddress((void**)&dXh, g_xh);
    cudaGetSymbolAddress((void**)&dXl, g_xl);
    cudaGetSymbolAddress((void**)&dAh, g_acth);
    cudaGetSymbolAddress((void**)&dAl, g_actl);
    cudaGetSymbolAddress((void**)&dW1h, g_w1h);
    cudaGetSymbolAddress((void**)&dW2h, g_w2h);
    cudaGetSymbolAddress((void**)&dAs, g_asrc);
    cudaGetSymbolAddress((void**)&dAd, g_adst);
    cudaGetSymbolAddress((void**)&dRow, g_rowptr);
    cudaGetSymbolAddress((void**)&dDeg, g_deg);
    cudaGetSymbolAddress((void**)&dCur, g_cursor);
    cudaGetSymbolAddress((void**)&dCsr, g_csrc);

    cudaFuncSetAttribute(gemm_f16_kernel,
                         cudaFuncAttributeMaxDynamicSharedMemorySize, GEMM_SMEM);

    static cudaStream_t s2 = [] { cudaStream_t s; cudaStreamCreate(&s); return s; }();
    static cudaEvent_t evFork = [] {
        cudaEvent_t e; cudaEventCreateWithFlags(&e, cudaEventDisableTiming); return e; }();
    static cudaEvent_t evJoin = [] {
        cudaEvent_t e; cudaEventCreateWithFlags(&e, cudaEventDisableTiming); return e; }();

    const int warpBlocks = (N * 32 + 255) / 256;
    dim3 gg((N + 127) / 128, HC / 128);

    // fork: CSR build on s2, concurrent with operand prep + GEMM1 on main
    cudaEventRecord(evFork, 0);
    cudaStreamWaitEvent(s2, evFork, 0);

    zero2_kernel<<<(N + 255) / 256, 256, 0, s2>>>(dDeg, dCur, N);
    hist_kernel<<<(E + 255) / 256, 256, 0, s2>>>(ei, E, dDeg);
    scan_kernel<<<1, 1024, 0, s2>>>(dDeg, dRow, N);
    scatter_kernel<<<(E + 255) / 256, 256, 0, s2>>>(ei, E, dRow, dCur, dCsr);
    cudaEventRecord(evJoin, s2);

    // operand prep (main stream)
    int xq = N * DIN / 4;
    split_x_kernel<<<(xq + 255) / 256, 256>>>(x, dXh, dXl, xq);
    round_w_kernel<<<(DIN * HC / 4 + 255) / 256, 256>>>(W1, dW1h, DIN * HC / 4);
    round_w_kernel<<<(HC * HC / 4 + 255) / 256, 256>>>(W2, dW2h, HC * HC / 4);

    // layer 1 GEMM (+ fused attention coefficients)
    gemm_f16_kernel<<<gg, 256, GEMM_SMEM>>>(dXh, dXl, dW1h, dH, as1, ad1,
                                            dAs, dAd, N, DIN, HC);

    // join: aggregation needs the CSR
    cudaStreamWaitEvent(0, evJoin, 0);
    agg1_kernel<<<warpBlocks, 256>>>(dH, dAs, dAd, dRow, dCsr, b1, dAh, dAl, N);

    // layer 2
    gemm_f16_kernel<<<gg, 256, GEMM_SMEM>>>(dAh, dAl, dW2h, dH, as2, ad2,
                                            dAs, dAd, N, HC, HC);
    agg2_kernel<<<warpBlocks, 256>>>(dH, dAs, dAd, dRow, dCsr, b2, out, N);
}